// round 1
// baseline (speedup 1.0000x reference)
#include <cuda_runtime.h>
#include <math.h>

// Problem constants
#define BB 16
#define LL 512
#define DD 512
#define DH 256          // D_IN_HALF
#define G4 2048         // 4*D_MODEL
#define PP (BB*LL)      // 8192 rows
#define KS 9

// ---------------------------------------------------------------------------
// Scratch (device globals: allocation-free per harness rules)
// ---------------------------------------------------------------------------
__device__ float g_glu[PP * DH];     //  8 MB  GLU output
__device__ float g_y[PP * DD];       // 16 MB  conv projection output
__device__ float g_gx[PP * G4];      // 64 MB  x-side gates (incl. b_ih)
__device__ float g_gates[PP * G4];   // 64 MB  h-side gates per step
__device__ float g_h[PP * DD];       // 16 MB  hidden state
__device__ float g_c[PP * DD];       // 16 MB  cell state

// ---------------------------------------------------------------------------
// f32x2 packed-FMA helpers (Blackwell FFMA2: 2x fp32 throughput vs FFMA)
// ---------------------------------------------------------------------------
__device__ __forceinline__ unsigned long long pack_f32x2(float lo, float hi) {
    unsigned long long r;
    asm("mov.b64 %0, {%1, %2};" : "=l"(r) : "f"(lo), "f"(hi));
    return r;
}
__device__ __forceinline__ void ffma2(unsigned long long& d,
                                      unsigned long long a,
                                      unsigned long long b) {
    asm("fma.rn.f32x2 %0, %1, %2, %0;" : "+l"(d) : "l"(a), "l"(b));
}
__device__ __forceinline__ float2 unpack_f32x2(unsigned long long v) {
    float2 f;
    asm("mov.b64 {%0, %1}, %2;" : "=f"(f.x), "=f"(f.y) : "l"(v));
    return f;
}

__device__ __forceinline__ float sigf(float x) {
    return 1.0f / (1.0f + expf(-x));
}

// ---------------------------------------------------------------------------
// GLU: g_glu[p,c] = x[p,c] * sigmoid(x[p,256+c])
// ---------------------------------------------------------------------------
__global__ void glu_kernel(const float* __restrict__ x) {
    int i = blockIdx.x * blockDim.x + threadIdx.x;
    if (i >= PP * DH) return;
    int p = i / DH;
    int c = i - p * DH;
    float a = x[p * (2 * DH) + c];
    float b = x[p * (2 * DH) + DH + c];
    g_glu[i] = a * sigf(b);
}

// ---------------------------------------------------------------------------
// Tiled fp32 GEMM with FFMA2:  C[M,N] = A[M,K] * Bw[N,K]^T  (+ bias[N])
// A, Bw both K-contiguous (row-major).  BM=BN=128, BK=16, 256 thr, 8x8/thread.
// All shapes here are multiples of the tile sizes -> no bounds checks.
// ---------------------------------------------------------------------------
#define BM 128
#define BN 128
#define BK 16
#define TM 8
#define TN 8

template <int M, int N, int K, bool BIAS>
__global__ __launch_bounds__(256, 2) void gemm_tn(const float* __restrict__ A,
                                                  const float* __restrict__ Bw,
                                                  const float* __restrict__ bias,
                                                  float* __restrict__ C) {
    __shared__ float As[BK][BM];
    __shared__ float Bs[BK][BN];

    const int tid = threadIdx.x;
    const int m0 = blockIdx.y * BM;
    const int n0 = blockIdx.x * BN;

    // loader: thread -> (row lr within 64, 4-float column chunk lq)
    const int lr = tid >> 2;         // 0..63
    const int lq = (tid & 3) * 4;    // 0,4,8,12

    // compute: 16x16 thread grid, each owns 8 rows x 8 cols (4 f32x2 pairs)
    const int trow = (tid >> 4) * TM;  // 0..120
    const int tcol = (tid & 15) * TN;  // 0..120

    unsigned long long acc[TM][TN / 2];
#pragma unroll
    for (int i = 0; i < TM; i++)
#pragma unroll
        for (int j = 0; j < TN / 2; j++) acc[i][j] = 0ull;

#pragma unroll 1
    for (int k0 = 0; k0 < K; k0 += BK) {
        // load A and B tiles (transposed into [k][m]/[k][n])
#pragma unroll
        for (int h = 0; h < 2; h++) {
            int r = lr + h * 64;
            float4 va = *(const float4*)&A[(m0 + r) * K + k0 + lq];
            As[lq + 0][r] = va.x;
            As[lq + 1][r] = va.y;
            As[lq + 2][r] = va.z;
            As[lq + 3][r] = va.w;
            float4 vb = *(const float4*)&Bw[(n0 + r) * K + k0 + lq];
            Bs[lq + 0][r] = vb.x;
            Bs[lq + 1][r] = vb.y;
            Bs[lq + 2][r] = vb.z;
            Bs[lq + 3][r] = vb.w;
        }
        __syncthreads();

#pragma unroll
        for (int k = 0; k < BK; k++) {
            unsigned long long bv[TN / 2];
#pragma unroll
            for (int j = 0; j < TN / 2; j++) {
                float2 b2 = *(const float2*)&Bs[k][tcol + 2 * j];
                bv[j] = pack_f32x2(b2.x, b2.y);
            }
            float av[TM];
#pragma unroll
            for (int i = 0; i < TM; i += 4) {
                float4 a4 = *(const float4*)&As[k][trow + i];
                av[i + 0] = a4.x; av[i + 1] = a4.y;
                av[i + 2] = a4.z; av[i + 3] = a4.w;
            }
#pragma unroll
            for (int i = 0; i < TM; i++) {
                unsigned long long ap = pack_f32x2(av[i], av[i]);
#pragma unroll
                for (int j = 0; j < TN / 2; j++) ffma2(acc[i][j], ap, bv[j]);
            }
        }
        __syncthreads();
    }

#pragma unroll
    for (int i = 0; i < TM; i++) {
#pragma unroll
        for (int j = 0; j < TN / 2; j++) {
            float2 v = unpack_f32x2(acc[i][j]);
            int n = n0 + tcol + 2 * j;
            if (BIAS) {
                v.x += bias[n];
                v.y += bias[n + 1];
            }
            *(float2*)&C[(m0 + trow + i) * N + n] = v;
        }
    }
}

// ---------------------------------------------------------------------------
// LSTM cell update for one step.
//   gates = Gx[p + step - 8] (or b_ih if OOB) + (step>0 ? g_gates[p] : 0) + b_hh
//   c = sig(f)*c + sig(i)*tanh(g);  h = sig(o)*tanh(c)
// step==8 writes h to d_out.
// ---------------------------------------------------------------------------
__global__ void cell_kernel(const float* __restrict__ b_ih,
                            const float* __restrict__ b_hh,
                            float* __restrict__ out, int step) {
    int i = blockIdx.x * blockDim.x + threadIdx.x;
    if (i >= PP * DD) return;
    int p = i >> 9;       // row (b*512 + l)
    int d = i & 511;
    int l = p & 511;

    float gi, gf, gg, go;
    int src = l + step - (KS - 1);
    if (src >= 0) {
        const float* gx = &g_gx[(p + step - (KS - 1)) * G4];
        gi = gx[d];
        gf = gx[512 + d];
        gg = gx[1024 + d];
        go = gx[1536 + d];
    } else {
        gi = b_ih[d];
        gf = b_ih[512 + d];
        gg = b_ih[1024 + d];
        go = b_ih[1536 + d];
    }
    if (step > 0) {
        const float* gh = &g_gates[p * G4];
        gi += gh[d];
        gf += gh[512 + d];
        gg += gh[1024 + d];
        go += gh[1536 + d];
    }
    gi += b_hh[d];
    gf += b_hh[512 + d];
    gg += b_hh[1024 + d];
    go += b_hh[1536 + d];

    float c_old = (step > 0) ? g_c[i] : 0.0f;
    float c = sigf(gf) * c_old + sigf(gi) * tanhf(gg);
    float h = sigf(go) * tanhf(c);
    g_c[i] = c;
    if (step == KS - 1)
        out[i] = h;
    else
        g_h[i] = h;
}

// ---------------------------------------------------------------------------
// Launch
// ---------------------------------------------------------------------------
extern "C" void kernel_launch(void* const* d_in, const int* in_sizes, int n_in,
                              void* d_out, int out_size) {
    const float* x      = (const float*)d_in[0];
    const float* conv_w = (const float*)d_in[1];
    const float* conv_b = (const float*)d_in[2];
    const float* w_ih   = (const float*)d_in[3];
    const float* w_hh   = (const float*)d_in[4];
    const float* b_ih   = (const float*)d_in[5];
    const float* b_hh   = (const float*)d_in[6];
    float* out = (float*)d_out;

    float *p_glu, *p_y, *p_gx, *p_gates, *p_h;
    cudaGetSymbolAddress((void**)&p_glu, g_glu);
    cudaGetSymbolAddress((void**)&p_y, g_y);
    cudaGetSymbolAddress((void**)&p_gx, g_gx);
    cudaGetSymbolAddress((void**)&p_gates, g_gates);
    cudaGetSymbolAddress((void**)&p_h, g_h);

    // 1) GLU
    glu_kernel<<<(PP * DH + 255) / 256, 256>>>(x);

    // 2) y = glu @ conv_w^T + conv_b   (8192 x 512 x 256)
    {
        dim3 grid(DD / BN, PP / BM);
        gemm_tn<PP, DD, DH, true><<<grid, 256>>>(p_glu, conv_w, conv_b, p_y);
    }

    // 3) Gx = y @ w_ih^T + b_ih        (8192 x 2048 x 512)  -- shared across steps
    {
        dim3 grid(G4 / BN, PP / BM);
        gemm_tn<PP, G4, DD, true><<<grid, 256>>>(p_y, w_ih, b_ih, p_gx);
    }

    // 4) step 0: h==0, no recurrent GEMM
    cell_kernel<<<(PP * DD + 255) / 256, 256>>>(b_ih, b_hh, out, 0);

    // 5) steps 1..8: gates_h = h @ w_hh^T, then cell update
    for (int step = 1; step < KS; step++) {
        dim3 grid(G4 / BN, PP / BM);
        gemm_tn<PP, G4, DD, false><<<grid, 256>>>(p_h, w_hh, nullptr, p_gates);
        cell_kernel<<<(PP * DD + 255) / 256, 256>>>(b_ih, b_hh, out, step);
    }
}

// round 2
// speedup vs baseline: 1.0011x; 1.0011x over previous
#include <cuda_runtime.h>
#include <math.h>

// Problem constants
#define BB 16
#define LL 512
#define DD 512
#define DH 256          // D_IN_HALF
#define G4 2048         // 4*D_MODEL
#define PP (BB*LL)      // 8192 rows
#define KS 9

// ---------------------------------------------------------------------------
// Scratch (device globals: allocation-free per harness rules)
// ---------------------------------------------------------------------------
__device__ float g_glu[PP * DH];     //  8 MB  GLU output
__device__ float g_y[PP * DD];       // 16 MB  conv projection output
__device__ float g_gx[PP * G4];      // 64 MB  x-side gates (incl. b_ih)
__device__ float g_gates[PP * G4];   // 64 MB  h-side gates per step
__device__ float g_h[PP * DD];       // 16 MB  hidden state
__device__ float g_c[PP * DD];       // 16 MB  cell state

// ---------------------------------------------------------------------------
// f32x2 packed-FMA helpers (Blackwell FFMA2: 2x fp32 throughput vs FFMA)
// ---------------------------------------------------------------------------
__device__ __forceinline__ unsigned long long pack_f32x2(float lo, float hi) {
    unsigned long long r;
    asm("mov.b64 %0, {%1, %2};" : "=l"(r) : "f"(lo), "f"(hi));
    return r;
}
__device__ __forceinline__ void ffma2(unsigned long long& d,
                                      unsigned long long a,
                                      unsigned long long b) {
    asm("fma.rn.f32x2 %0, %1, %2, %0;" : "+l"(d) : "l"(a), "l"(b));
}
__device__ __forceinline__ float2 unpack_f32x2(unsigned long long v) {
    float2 f;
    asm("mov.b64 {%0, %1}, %2;" : "=f"(f.x), "=f"(f.y) : "l"(v));
    return f;
}

__device__ __forceinline__ float sigf(float x) {
    return 1.0f / (1.0f + expf(-x));
}

// ---------------------------------------------------------------------------
// GLU: g_glu[p,c] = x[p,c] * sigmoid(x[p,256+c])
// ---------------------------------------------------------------------------
__global__ void glu_kernel(const float* __restrict__ x) {
    int i = blockIdx.x * blockDim.x + threadIdx.x;
    if (i >= PP * DH) return;
    int p = i / DH;
    int c = i - p * DH;
    float a = x[p * (2 * DH) + c];
    float b = x[p * (2 * DH) + DH + c];
    g_glu[i] = a * sigf(b);
}

// ---------------------------------------------------------------------------
// Tiled fp32 GEMM with FFMA2:  C[M,N] = A[M,K] * Bw[N,K]^T  (+ bias[N])
// A, Bw both K-contiguous (row-major).  BM=BN=128, BK=16, 256 thr, 8x8/thread.
// All shapes here are multiples of the tile sizes -> no bounds checks.
// ---------------------------------------------------------------------------
#define BM 128
#define BN 128
#define BK 16
#define TM 8
#define TN 8

template <int M, int N, int K, bool BIAS>
__global__ __launch_bounds__(256, 2) void gemm_tn(const float* __restrict__ A,
                                                  const float* __restrict__ Bw,
                                                  const float* __restrict__ bias,
                                                  float* __restrict__ C) {
    __shared__ float As[BK][BM];
    __shared__ float Bs[BK][BN];

    const int tid = threadIdx.x;
    const int m0 = blockIdx.y * BM;
    const int n0 = blockIdx.x * BN;

    // loader: thread -> (row lr within 64, 4-float column chunk lq)
    const int lr = tid >> 2;         // 0..63
    const int lq = (tid & 3) * 4;    // 0,4,8,12

    // compute: 16x16 thread grid, each owns 8 rows x 8 cols (4 f32x2 pairs)
    const int trow = (tid >> 4) * TM;  // 0..120
    const int tcol = (tid & 15) * TN;  // 0..120

    unsigned long long acc[TM][TN / 2];
#pragma unroll
    for (int i = 0; i < TM; i++)
#pragma unroll
        for (int j = 0; j < TN / 2; j++) acc[i][j] = 0ull;

#pragma unroll 1
    for (int k0 = 0; k0 < K; k0 += BK) {
        // load A and B tiles (transposed into [k][m]/[k][n])
#pragma unroll
        for (int h = 0; h < 2; h++) {
            int r = lr + h * 64;
            float4 va = *(const float4*)&A[(m0 + r) * K + k0 + lq];
            As[lq + 0][r] = va.x;
            As[lq + 1][r] = va.y;
            As[lq + 2][r] = va.z;
            As[lq + 3][r] = va.w;
            float4 vb = *(const float4*)&Bw[(n0 + r) * K + k0 + lq];
            Bs[lq + 0][r] = vb.x;
            Bs[lq + 1][r] = vb.y;
            Bs[lq + 2][r] = vb.z;
            Bs[lq + 3][r] = vb.w;
        }
        __syncthreads();

#pragma unroll
        for (int k = 0; k < BK; k++) {
            unsigned long long bv[TN / 2];
#pragma unroll
            for (int j = 0; j < TN / 2; j++) {
                float2 b2 = *(const float2*)&Bs[k][tcol + 2 * j];
                bv[j] = pack_f32x2(b2.x, b2.y);
            }
            float av[TM];
#pragma unroll
            for (int i = 0; i < TM; i += 4) {
                float4 a4 = *(const float4*)&As[k][trow + i];
                av[i + 0] = a4.x; av[i + 1] = a4.y;
                av[i + 2] = a4.z; av[i + 3] = a4.w;
            }
#pragma unroll
            for (int i = 0; i < TM; i++) {
                unsigned long long ap = pack_f32x2(av[i], av[i]);
#pragma unroll
                for (int j = 0; j < TN / 2; j++) ffma2(acc[i][j], ap, bv[j]);
            }
        }
        __syncthreads();
    }

#pragma unroll
    for (int i = 0; i < TM; i++) {
#pragma unroll
        for (int j = 0; j < TN / 2; j++) {
            float2 v = unpack_f32x2(acc[i][j]);
            int n = n0 + tcol + 2 * j;
            if (BIAS) {
                v.x += bias[n];
                v.y += bias[n + 1];
            }
            *(float2*)&C[(m0 + trow + i) * N + n] = v;
        }
    }
}

// ---------------------------------------------------------------------------
// LSTM cell update for one step.
//   gates = Gx[p + step - 8] (or b_ih if OOB) + (step>0 ? g_gates[p] : 0) + b_hh
//   c = sig(f)*c + sig(i)*tanh(g);  h = sig(o)*tanh(c)
// step==8 writes h to d_out.
// ---------------------------------------------------------------------------
__global__ void cell_kernel(const float* __restrict__ b_ih,
                            const float* __restrict__ b_hh,
                            float* __restrict__ out, int step) {
    int i = blockIdx.x * blockDim.x + threadIdx.x;
    if (i >= PP * DD) return;
    int p = i >> 9;       // row (b*512 + l)
    int d = i & 511;
    int l = p & 511;

    float gi, gf, gg, go;
    int src = l + step - (KS - 1);
    if (src >= 0) {
        const float* gx = &g_gx[(p + step - (KS - 1)) * G4];
        gi = gx[d];
        gf = gx[512 + d];
        gg = gx[1024 + d];
        go = gx[1536 + d];
    } else {
        gi = b_ih[d];
        gf = b_ih[512 + d];
        gg = b_ih[1024 + d];
        go = b_ih[1536 + d];
    }
    if (step > 0) {
        const float* gh = &g_gates[p * G4];
        gi += gh[d];
        gf += gh[512 + d];
        gg += gh[1024 + d];
        go += gh[1536 + d];
    }
    gi += b_hh[d];
    gf += b_hh[512 + d];
    gg += b_hh[1024 + d];
    go += b_hh[1536 + d];

    float c_old = (step > 0) ? g_c[i] : 0.0f;
    float c = sigf(gf) * c_old + sigf(gi) * tanhf(gg);
    float h = sigf(go) * tanhf(c);
    g_c[i] = c;
    if (step == KS - 1)
        out[i] = h;
    else
        g_h[i] = h;
}

// ---------------------------------------------------------------------------
// Launch
// ---------------------------------------------------------------------------
extern "C" void kernel_launch(void* const* d_in, const int* in_sizes, int n_in,
                              void* d_out, int out_size) {
    const float* x      = (const float*)d_in[0];
    const float* conv_w = (const float*)d_in[1];
    const float* conv_b = (const float*)d_in[2];
    const float* w_ih   = (const float*)d_in[3];
    const float* w_hh   = (const float*)d_in[4];
    const float* b_ih   = (const float*)d_in[5];
    const float* b_hh   = (const float*)d_in[6];
    float* out = (float*)d_out;

    float *p_glu, *p_y, *p_gx, *p_gates, *p_h;
    cudaGetSymbolAddress((void**)&p_glu, g_glu);
    cudaGetSymbolAddress((void**)&p_y, g_y);
    cudaGetSymbolAddress((void**)&p_gx, g_gx);
    cudaGetSymbolAddress((void**)&p_gates, g_gates);
    cudaGetSymbolAddress((void**)&p_h, g_h);

    // 1) GLU
    glu_kernel<<<(PP * DH + 255) / 256, 256>>>(x);

    // 2) y = glu @ conv_w^T + conv_b   (8192 x 512 x 256)
    {
        dim3 grid(DD / BN, PP / BM);
        gemm_tn<PP, DD, DH, true><<<grid, 256>>>(p_glu, conv_w, conv_b, p_y);
    }

    // 3) Gx = y @ w_ih^T + b_ih        (8192 x 2048 x 512)  -- shared across steps
    {
        dim3 grid(G4 / BN, PP / BM);
        gemm_tn<PP, G4, DD, true><<<grid, 256>>>(p_y, w_ih, b_ih, p_gx);
    }

    // 4) step 0: h==0, no recurrent GEMM
    cell_kernel<<<(PP * DD + 255) / 256, 256>>>(b_ih, b_hh, out, 0);

    // 5) steps 1..8: gates_h = h @ w_hh^T, then cell update
    for (int step = 1; step < KS; step++) {
        dim3 grid(G4 / BN, PP / BM);
        gemm_tn<PP, G4, DD, false><<<grid, 256>>>(p_h, w_hh, nullptr, p_gates);
        cell_kernel<<<(PP * DD + 255) / 256, 256>>>(b_ih, b_hh, out, step);
    }
}

// round 4
// speedup vs baseline: 2.6103x; 2.6075x over previous
#include <cuda_runtime.h>
#include <cuda_bf16.h>
#include <math.h>
#include <stdint.h>

// Problem constants
#define BB 16
#define LL 512
#define DD 512
#define DH 256          // D_IN_HALF
#define G4 2048         // 4*D_MODEL
#define PP (BB*LL)      // 8192 rows
#define KS 9
#define K3D (3*DD)      // 1536
#define K3H (3*DH)      // 768

// ---------------------------------------------------------------------------
// Scratch (device globals; allocation-free per harness rules)
// ---------------------------------------------------------------------------
__device__ __nv_bfloat16 g_glu3[(size_t)PP * K3H];   // 12MB
__device__ float         g_y[(size_t)PP * DD];       // 16MB
__device__ __nv_bfloat16 g_y3[(size_t)PP * K3D];     // 24MB
__device__ __nv_bfloat16 g_h3[(size_t)PP * K3D];     // 24MB
__device__ float         g_gx[(size_t)PP * G4];      // 64MB
__device__ float         g_gates[(size_t)PP * G4];   // 64MB
__device__ float         g_c[(size_t)PP * DD];       // 16MB
__device__ __nv_bfloat16 g_wih3[(size_t)G4 * K3D];   //  6MB
__device__ __nv_bfloat16 g_whh3[(size_t)G4 * K3D];   //  6MB
__device__ __nv_bfloat16 g_wcv3[(size_t)DD * K3H];   //  0.75MB

// ---------------------------------------------------------------------------
// helpers
// ---------------------------------------------------------------------------
__device__ __forceinline__ uint32_t s2u(const void* p) {
    uint32_t a;
    asm("{ .reg .u64 t; cvta.to.shared.u64 t, %1; cvt.u32.u64 %0, t; }"
        : "=r"(a) : "l"(p));
    return a;
}
__device__ __forceinline__ float sigf(float x) { return 1.0f / (1.0f + expf(-x)); }
__device__ __forceinline__ void split2(float v, __nv_bfloat16& hi, __nv_bfloat16& lo) {
    hi = __float2bfloat16_rn(v);
    lo = __float2bfloat16_rn(v - __bfloat162float(hi));
}

#define LDSM4(r0, r1, r2, r3, addr)                                            \
    asm volatile("ldmatrix.sync.aligned.m8n8.x4.shared.b16 {%0,%1,%2,%3}, [%4];" \
                 : "=r"(r0), "=r"(r1), "=r"(r2), "=r"(r3) : "r"(addr))

#define MMA16816(c, a, b0, b1)                                                 \
    asm volatile("mma.sync.aligned.m16n8k16.row.col.f32.bf16.bf16.f32 "        \
                 "{%0,%1,%2,%3},{%4,%5,%6,%7},{%8,%9},{%0,%1,%2,%3};"          \
                 : "+f"((c)[0]), "+f"((c)[1]), "+f"((c)[2]), "+f"((c)[3])      \
                 : "r"((a)[0]), "r"((a)[1]), "r"((a)[2]), "r"((a)[3]),         \
                   "r"(b0), "r"(b1))

#define CPASYNC16(dst, src)                                                    \
    asm volatile("cp.async.cg.shared.global [%0], [%1], 16;" :: "r"(dst), "l"(src))
#define CPCOMMIT() asm volatile("cp.async.commit_group;" ::: "memory")
#define CPWAIT(n)  asm volatile("cp.async.wait_group %0;" :: "n"(n) : "memory")

// ---------------------------------------------------------------------------
// bf16 mma.sync GEMM:  C[M, NTOT] = A'[M, KT] * B'[NTOT, KT]^T (+ bias)
// CTA 128x128, BK=64 bf16 (128B rows, SW128 swizzle), 8 warps (4m x 2n),
// warp tile 32x64, 3-stage cp.async pipeline.
// ---------------------------------------------------------------------------
#define STAGE_BYTES 32768           // A 16KB + B 16KB
#define SMEM_BYTES (3 * STAGE_BYTES)

template <int KT, int NTOT, bool BIAS>
__global__ void __launch_bounds__(256, 2)
gemm_mma(const __nv_bfloat16* __restrict__ A,
         const __nv_bfloat16* __restrict__ B,
         const float* __restrict__ bias,
         float* __restrict__ C) {
    extern __shared__ char smem[];
    const uint32_t sb = s2u(smem);
    const int tid = threadIdx.x;
    const int wid = tid >> 5;
    const int lane = tid & 31;
    const int m0 = blockIdx.y * 128;
    const int n0 = blockIdx.x * 128;
    const int wm = (wid >> 1) * 32;   // 0,32,64,96
    const int wn = (wid & 1) * 64;    // 0,64

    constexpr int NKC = KT / 64;

    // loader mapping: q = tid + t*256 -> row = q>>3 (0..127), chunk c = q&7
    const int lrow8 = tid >> 3;       // base row for loads
    const int lc = (tid & 7) * 16;    // byte chunk within 128B row

    auto load_stage = [&](int kc, int s) {
        uint32_t sA = sb + s * STAGE_BYTES;
        uint32_t sB = sA + 16384;
        int k0 = kc * 64;             // bf16 k offset
#pragma unroll
        for (int t = 0; t < 4; t++) {
            int row = lrow8 + t * 32;
            uint32_t swz = (uint32_t)((row & 7) << 4);
            uint32_t off = (uint32_t)(row * 128) + ((uint32_t)lc ^ swz);
            CPASYNC16(sA + off, A + (size_t)(m0 + row) * KT + k0 + (lc >> 1));
            CPASYNC16(sB + off, B + (size_t)(n0 + row) * KT + k0 + (lc >> 1));
        }
    };

    // prologue: stages 0,1
    load_stage(0, 0); CPCOMMIT();
    load_stage(1, 1); CPCOMMIT();

    float acc[2][8][4];
#pragma unroll
    for (int i = 0; i < 2; i++)
#pragma unroll
        for (int j = 0; j < 8; j++)
#pragma unroll
            for (int q = 0; q < 4; q++) acc[i][j][q] = 0.0f;

    // ldmatrix lane addressing
    const int lr16 = lane & 15;                 // row within 16-row tile
    const uint32_t lhi = (uint32_t)((lane >> 4) * 16);  // k-half selector (bytes)
    const uint32_t lswz = (uint32_t)((lr16 & 7) << 4);

#pragma unroll 1
    for (int kc = 0; kc < NKC; kc++) {
        __syncthreads();
        if (kc + 2 < NKC) {
            load_stage(kc + 2, (kc + 2) % 3);
            CPCOMMIT();
            CPWAIT(2);
        } else if (kc + 1 < NKC) {
            CPWAIT(1);
        } else {
            CPWAIT(0);
        }
        __syncthreads();

        uint32_t sA = sb + (kc % 3) * STAGE_BYTES;
        uint32_t sB = sA + 16384;

#pragma unroll
        for (int k16 = 0; k16 < 4; k16++) {
            uint32_t colb = ((uint32_t)(k16 * 32) + lhi) ^ lswz;
            uint32_t a[2][4];
#pragma unroll
            for (int mt = 0; mt < 2; mt++) {
                uint32_t addr = sA + (uint32_t)((wm + mt * 16 + lr16) * 128) + colb;
                LDSM4(a[mt][0], a[mt][1], a[mt][2], a[mt][3], addr);
            }
            uint32_t br[4][4];
#pragma unroll
            for (int g = 0; g < 4; g++) {
                uint32_t addr = sB + (uint32_t)((wn + g * 16 + lr16) * 128) + colb;
                LDSM4(br[g][0], br[g][1], br[g][2], br[g][3], addr);
            }
#pragma unroll
            for (int mt = 0; mt < 2; mt++)
#pragma unroll
                for (int g = 0; g < 4; g++) {
                    MMA16816(acc[mt][2 * g + 0], a[mt], br[g][0], br[g][2]);
                    MMA16816(acc[mt][2 * g + 1], a[mt], br[g][1], br[g][3]);
                }
        }
    }

    // epilogue
    const int qrow = lane >> 2;
    const int qcol = (lane & 3) * 2;
#pragma unroll
    for (int mt = 0; mt < 2; mt++) {
#pragma unroll
        for (int nt = 0; nt < 8; nt++) {
            int row = m0 + wm + mt * 16 + qrow;
            int col = n0 + wn + nt * 8 + qcol;
            float bx = 0.f, by = 0.f;
            if (BIAS) { bx = __ldg(&bias[col]); by = __ldg(&bias[col + 1]); }
            float2 v0 = make_float2(acc[mt][nt][0] + bx, acc[mt][nt][1] + by);
            float2 v1 = make_float2(acc[mt][nt][2] + bx, acc[mt][nt][3] + by);
            *(float2*)&C[(size_t)row * NTOT + col] = v0;
            *(float2*)&C[(size_t)(row + 8) * NTOT + col] = v1;
        }
    }
}

// ---------------------------------------------------------------------------
// Elementwise kernels
// ---------------------------------------------------------------------------
__global__ void glu3_kernel(const float* __restrict__ x) {
    int i = blockIdx.x * blockDim.x + threadIdx.x;
    if (i >= PP * DH) return;
    int p = i >> 8;
    int c = i & 255;
    float a = x[p * 512 + c];
    float b = x[p * 512 + 256 + c];
    float v = a * sigf(b);
    __nv_bfloat16 hi, lo;
    split2(v, hi, lo);
    size_t base = (size_t)p * K3H;
    g_glu3[base + c] = hi;
    g_glu3[base + 256 + c] = hi;
    g_glu3[base + 512 + c] = lo;
}

__global__ void wsplit_kernel(const float* __restrict__ w,
                              __nv_bfloat16* __restrict__ dst, int K, int total) {
    int i = blockIdx.x * blockDim.x + threadIdx.x;
    if (i >= total) return;
    int n = i / K;
    int k = i - n * K;
    __nv_bfloat16 hi, lo;
    split2(w[i], hi, lo);
    size_t base = (size_t)n * 3 * K;
    dst[base + k] = hi;
    dst[base + K + k] = lo;
    dst[base + 2 * K + k] = hi;
}

__global__ void ysplit_kernel() {
    int i = blockIdx.x * blockDim.x + threadIdx.x;
    if (i >= PP * DD) return;
    int p = i >> 9;
    int d = i & 511;
    __nv_bfloat16 hi, lo;
    split2(g_y[i], hi, lo);
    size_t base = (size_t)p * K3D;
    g_y3[base + d] = hi;
    g_y3[base + 512 + d] = hi;
    g_y3[base + 1024 + d] = lo;
}

__global__ void cell_kernel(const float* __restrict__ b_ih,
                            const float* __restrict__ b_hh,
                            float* __restrict__ out, int step) {
    int i = blockIdx.x * blockDim.x + threadIdx.x;
    if (i >= PP * DD) return;
    int p = i >> 9;
    int d = i & 511;
    int l = p & 511;

    float gi, gf, gg, go;
    int src = l + step - (KS - 1);
    if (src >= 0) {
        const float* gx = &g_gx[(size_t)(p + step - (KS - 1)) * G4];
        gi = gx[d];
        gf = gx[512 + d];
        gg = gx[1024 + d];
        go = gx[1536 + d];
    } else {
        gi = b_ih[d];
        gf = b_ih[512 + d];
        gg = b_ih[1024 + d];
        go = b_ih[1536 + d];
    }
    if (step > 0) {
        const float* gh = &g_gates[(size_t)p * G4];
        gi += gh[d];
        gf += gh[512 + d];
        gg += gh[1024 + d];
        go += gh[1536 + d];
    }
    gi += b_hh[d];
    gf += b_hh[512 + d];
    gg += b_hh[1024 + d];
    go += b_hh[1536 + d];

    float c_old = (step > 0) ? g_c[i] : 0.0f;
    float c = sigf(gf) * c_old + sigf(gi) * tanhf(gg);
    float h = sigf(go) * tanhf(c);
    g_c[i] = c;
    if (step == KS - 1) {
        out[i] = h;
    } else {
        __nv_bfloat16 hi, lo;
        split2(h, hi, lo);
        size_t base = (size_t)p * K3D;
        g_h3[base + d] = hi;
        g_h3[base + 512 + d] = hi;
        g_h3[base + 1024 + d] = lo;
    }
}

// ---------------------------------------------------------------------------
// Launch
// ---------------------------------------------------------------------------
extern "C" void kernel_launch(void* const* d_in, const int* in_sizes, int n_in,
                              void* d_out, int out_size) {
    const float* x      = (const float*)d_in[0];
    const float* conv_w = (const float*)d_in[1];
    const float* conv_b = (const float*)d_in[2];
    const float* w_ih   = (const float*)d_in[3];
    const float* w_hh   = (const float*)d_in[4];
    const float* b_ih   = (const float*)d_in[5];
    const float* b_hh   = (const float*)d_in[6];
    float* out = (float*)d_out;

    __nv_bfloat16 *p_glu3, *p_y3, *p_h3, *p_wih3, *p_whh3, *p_wcv3;
    float *p_y, *p_gx, *p_gates;
    cudaGetSymbolAddress((void**)&p_glu3, g_glu3);
    cudaGetSymbolAddress((void**)&p_y, g_y);
    cudaGetSymbolAddress((void**)&p_y3, g_y3);
    cudaGetSymbolAddress((void**)&p_h3, g_h3);
    cudaGetSymbolAddress((void**)&p_gx, g_gx);
    cudaGetSymbolAddress((void**)&p_gates, g_gates);
    cudaGetSymbolAddress((void**)&p_wih3, g_wih3);
    cudaGetSymbolAddress((void**)&p_whh3, g_whh3);
    cudaGetSymbolAddress((void**)&p_wcv3, g_wcv3);

    cudaFuncSetAttribute(gemm_mma<K3H, DD, true>,
                         cudaFuncAttributeMaxDynamicSharedMemorySize, SMEM_BYTES);
    cudaFuncSetAttribute(gemm_mma<K3D, G4, true>,
                         cudaFuncAttributeMaxDynamicSharedMemorySize, SMEM_BYTES);
    cudaFuncSetAttribute(gemm_mma<K3D, G4, false>,
                         cudaFuncAttributeMaxDynamicSharedMemorySize, SMEM_BYTES);

    // 1) GLU + split
    glu3_kernel<<<(PP * DH + 255) / 256, 256>>>(x);

    // 2) weight splits
    wsplit_kernel<<<(G4 * DD + 255) / 256, 256>>>(w_ih, p_wih3, DD, G4 * DD);
    wsplit_kernel<<<(G4 * DD + 255) / 256, 256>>>(w_hh, p_whh3, DD, G4 * DD);
    wsplit_kernel<<<(DD * DH + 255) / 256, 256>>>(conv_w, p_wcv3, DH, DD * DH);

    // 3) y = glu @ conv_w^T + conv_b
    gemm_mma<K3H, DD, true><<<dim3(DD / 128, PP / 128), 256, SMEM_BYTES>>>(
        p_glu3, p_wcv3, conv_b, p_y);
    ysplit_kernel<<<(PP * DD + 255) / 256, 256>>>();

    // 4) Gx = y @ w_ih^T + b_ih
    gemm_mma<K3D, G4, true><<<dim3(G4 / 128, PP / 128), 256, SMEM_BYTES>>>(
        p_y3, p_wih3, b_ih, p_gx);

    // 5) step 0
    cell_kernel<<<(PP * DD + 255) / 256, 256>>>(b_ih, b_hh, out, 0);

    // 6) steps 1..8
    for (int step = 1; step < KS; step++) {
        gemm_mma<K3D, G4, false><<<dim3(G4 / 128, PP / 128), 256, SMEM_BYTES>>>(
            p_h3, p_whh3, nullptr, p_gates);
        cell_kernel<<<(PP * DD + 255) / 256, 256>>>(b_ih, b_hh, out, step);
    }
}

// round 5
// speedup vs baseline: 2.6852x; 1.0287x over previous
#include <cuda_runtime.h>
#include <cuda_bf16.h>
#include <math.h>
#include <stdint.h>

// Problem constants
#define BB 16
#define LL 512
#define DD 512
#define DH 256
#define G4 2048
#define PP (BB*LL)      // 8192
#define KS 9
#define K3D (3*DD)      // 1536
#define K3H (3*DH)      // 768

// ---------------------------------------------------------------------------
// Scratch
// ---------------------------------------------------------------------------
__device__ __nv_bfloat16 g_glu3[(size_t)PP * K3H];    // 12MB  A' of Gx GEMM
__device__ float         g_gx[(size_t)PP * G4];       // 64MB  gate-interleaved, incl b_ih
__device__ __nv_bfloat16 g_h3a[(size_t)PP * K3D];     // 24MB  h split, ping
__device__ __nv_bfloat16 g_h3b[(size_t)PP * K3D];     // 24MB  h split, pong
__device__ float         g_c[(size_t)PP * DD];        // 16MB  cell state
__device__ __nv_bfloat16 g_wih3[(size_t)G4 * K3D];    //  6MB  A' of Wf GEMM (interleaved rows)
__device__ __nv_bfloat16 g_whh3[(size_t)G4 * K3D];    //  6MB  B' of recurrent GEMM (interleaved)
__device__ __nv_bfloat16 g_cwT3[(size_t)DH * K3D];    //  .75MB B' of Wf GEMM (conv_w^T split)
__device__ float         g_wf[(size_t)G4 * DH];       //  2MB  Wf = w_ih @ conv_w (fp32)
__device__ __nv_bfloat16 g_wf3[(size_t)G4 * K3H];     //  3MB  B' of Gx GEMM
__device__ float         g_bf[G4];                    //  8KB  fused bias (interleaved)

// ---------------------------------------------------------------------------
// helpers
// ---------------------------------------------------------------------------
__device__ __forceinline__ uint32_t s2u(const void* p) {
    uint32_t a;
    asm("{ .reg .u64 t; cvta.to.shared.u64 t, %1; cvt.u32.u64 %0, t; }"
        : "=r"(a) : "l"(p));
    return a;
}
__device__ __forceinline__ float sigf(float x) { return 1.0f / (1.0f + expf(-x)); }
__device__ __forceinline__ void split2(float v, __nv_bfloat16& hi, __nv_bfloat16& lo) {
    hi = __float2bfloat16_rn(v);
    lo = __float2bfloat16_rn(v - __bfloat162float(hi));
}
__device__ __forceinline__ uint32_t pack_bf2(__nv_bfloat16 a, __nv_bfloat16 b) {
    __nv_bfloat162 t = __halves2bfloat162(a, b);
    return *(uint32_t*)&t;
}

#define LDSM4(r0, r1, r2, r3, addr)                                            \
    asm volatile("ldmatrix.sync.aligned.m8n8.x4.shared.b16 {%0,%1,%2,%3}, [%4];" \
                 : "=r"(r0), "=r"(r1), "=r"(r2), "=r"(r3) : "r"(addr))

#define MMA16816(c, a, b0, b1)                                                 \
    asm volatile("mma.sync.aligned.m16n8k16.row.col.f32.bf16.bf16.f32 "        \
                 "{%0,%1,%2,%3},{%4,%5,%6,%7},{%8,%9},{%0,%1,%2,%3};"          \
                 : "+f"((c)[0]), "+f"((c)[1]), "+f"((c)[2]), "+f"((c)[3])      \
                 : "r"((a)[0]), "r"((a)[1]), "r"((a)[2]), "r"((a)[3]),         \
                   "r"(b0), "r"(b1))

#define CPASYNC16(dst, src)                                                    \
    asm volatile("cp.async.cg.shared.global [%0], [%1], 16;" :: "r"(dst), "l"(src))
#define CPCOMMIT() asm volatile("cp.async.commit_group;" ::: "memory")
#define CPWAIT(n)  asm volatile("cp.async.wait_group %0;" :: "n"(n) : "memory")

// ---------------------------------------------------------------------------
// bf16 mma.sync GEMM, CTA 128x128, BK=64, 3-stage cp.async.
// EPI=0: C store (+direct bias).  EPI=1: fused LSTM cell epilogue.
// ---------------------------------------------------------------------------
#define STAGE_BYTES 32768
#define SMEM_BYTES (3 * STAGE_BYTES)

template <int KT, int NTOT, bool BIAS, int EPI>
__global__ void __launch_bounds__(256, 2)
gemm_mma(const __nv_bfloat16* __restrict__ A,
         const __nv_bfloat16* __restrict__ B,
         const float* __restrict__ bias,
         float* __restrict__ C,
         const float* __restrict__ gx,
         const float* __restrict__ b_ih,
         const float* __restrict__ b_hh,
         float* __restrict__ cbuf,
         __nv_bfloat16* __restrict__ h3out,
         float* __restrict__ out,
         int step) {
    extern __shared__ char smem[];
    const uint32_t sb = s2u(smem);
    const int tid = threadIdx.x;
    const int wid = tid >> 5;
    const int lane = tid & 31;
    const int m0 = blockIdx.y * 128;
    const int n0 = blockIdx.x * 128;
    const int wm = (wid >> 1) * 32;
    const int wn = (wid & 1) * 64;

    constexpr int NKC = KT / 64;

    const int lrow8 = tid >> 3;
    const int lc = (tid & 7) * 16;

    auto load_stage = [&](int kc, int s) {
        uint32_t sA = sb + s * STAGE_BYTES;
        uint32_t sB = sA + 16384;
        int k0 = kc * 64;
#pragma unroll
        for (int t = 0; t < 4; t++) {
            int row = lrow8 + t * 32;
            uint32_t swz = (uint32_t)((row & 7) << 4);
            uint32_t off = (uint32_t)(row * 128) + ((uint32_t)lc ^ swz);
            CPASYNC16(sA + off, A + (size_t)(m0 + row) * KT + k0 + (lc >> 1));
            CPASYNC16(sB + off, B + (size_t)(n0 + row) * KT + k0 + (lc >> 1));
        }
    };

    load_stage(0, 0); CPCOMMIT();
    load_stage(1, 1); CPCOMMIT();

    float acc[2][8][4];
#pragma unroll
    for (int i = 0; i < 2; i++)
#pragma unroll
        for (int j = 0; j < 8; j++)
#pragma unroll
            for (int q = 0; q < 4; q++) acc[i][j][q] = 0.0f;

    const int lr16 = lane & 15;
    const uint32_t lhi = (uint32_t)((lane >> 4) * 16);
    const uint32_t lswz = (uint32_t)((lr16 & 7) << 4);

#pragma unroll 1
    for (int kc = 0; kc < NKC; kc++) {
        __syncthreads();
        if (kc + 2 < NKC) {
            load_stage(kc + 2, (kc + 2) % 3);
            CPCOMMIT();
            CPWAIT(2);
        } else if (kc + 1 < NKC) {
            CPWAIT(1);
        } else {
            CPWAIT(0);
        }
        __syncthreads();

        uint32_t sA = sb + (kc % 3) * STAGE_BYTES;
        uint32_t sB = sA + 16384;

#pragma unroll
        for (int k16 = 0; k16 < 4; k16++) {
            uint32_t colb = ((uint32_t)(k16 * 32) + lhi) ^ lswz;
            uint32_t a[2][4];
#pragma unroll
            for (int mt = 0; mt < 2; mt++) {
                uint32_t addr = sA + (uint32_t)((wm + mt * 16 + lr16) * 128) + colb;
                LDSM4(a[mt][0], a[mt][1], a[mt][2], a[mt][3], addr);
            }
            uint32_t br[4][4];
#pragma unroll
            for (int g = 0; g < 4; g++) {
                uint32_t addr = sB + (uint32_t)((wn + g * 16 + lr16) * 128) + colb;
                LDSM4(br[g][0], br[g][1], br[g][2], br[g][3], addr);
            }
#pragma unroll
            for (int mt = 0; mt < 2; mt++)
#pragma unroll
                for (int g = 0; g < 4; g++) {
                    MMA16816(acc[mt][2 * g + 0], a[mt], br[g][0], br[g][2]);
                    MMA16816(acc[mt][2 * g + 1], a[mt], br[g][1], br[g][3]);
                }
        }
    }

    if constexpr (EPI == 0) {
        const int qrow = lane >> 2;
        const int qcol = (lane & 3) * 2;
#pragma unroll
        for (int mt = 0; mt < 2; mt++) {
#pragma unroll
            for (int nt = 0; nt < 8; nt++) {
                int row = m0 + wm + mt * 16 + qrow;
                int col = n0 + wn + nt * 8 + qcol;
                float bx = 0.f, by = 0.f;
                if (BIAS) { bx = __ldg(&bias[col]); by = __ldg(&bias[col + 1]); }
                float2 v0 = make_float2(acc[mt][nt][0] + bx, acc[mt][nt][1] + by);
                float2 v1 = make_float2(acc[mt][nt][2] + bx, acc[mt][nt][3] + by);
                *(float2*)&C[(size_t)row * NTOT + col] = v0;
                *(float2*)&C[(size_t)(row + 8) * NTOT + col] = v1;
            }
        }
    } else {
        // -------- fused LSTM cell epilogue --------
        float* sh_h = (float*)smem;                 // [128][32]
        float* sh_c = (float*)(smem + 16384);       // [128][32]
        __syncthreads();
        // cooperative coalesced load of c_old
        {
            int rl = tid >> 1, half = (tid & 1) * 16;
            const float4* src = (const float4*)&cbuf[(size_t)(m0 + rl) * DD + (n0 >> 2) + half];
            float4* dst = (float4*)&sh_c[rl * 32 + half];
#pragma unroll
            for (int j = 0; j < 4; j++) dst[j] = src[j];
        }
        __syncthreads();

        const int qrow = lane >> 2;
        const bool odd = lane & 1;
#pragma unroll
        for (int mt = 0; mt < 2; mt++) {
#pragma unroll
            for (int nt = 0; nt < 8; nt++) {
                float* a = acc[mt][nt];
                float e0 = __shfl_xor_sync(0xFFFFFFFFu, a[0], 1);
                float e1 = __shfl_xor_sync(0xFFFFFFFFu, a[1], 1);
                float e2 = __shfl_xor_sync(0xFFFFFFFFu, a[2], 1);
                float e3 = __shfl_xor_sync(0xFFFFFFFFu, a[3], 1);
                float gi, gf, gg, go;
                if (!odd) { gi = a[0]; gf = a[1]; gg = e0; go = e1; }
                else      { gi = e2;   gf = e3;   gg = a[2]; go = a[3]; }
                int rl = wm + mt * 16 + qrow + (odd ? 8 : 0);
                int dl = (wn >> 2) + nt * 2 + ((lane & 3) >> 1);
                int p = m0 + rl;
                int d = (n0 >> 2) + dl;
                int l = p & 511;
                float4 q;
                if (l + step - 8 >= 0) {
                    q = *(const float4*)&gx[(size_t)(p + step - 8) * G4 + 4 * d];
                } else {
                    q.x = __ldg(&b_ih[d]);
                    q.y = __ldg(&b_ih[512 + d]);
                    q.z = __ldg(&b_ih[1024 + d]);
                    q.w = __ldg(&b_ih[1536 + d]);
                }
                gi += q.x + __ldg(&b_hh[d]);
                gf += q.y + __ldg(&b_hh[512 + d]);
                gg += q.z + __ldg(&b_hh[1024 + d]);
                go += q.w + __ldg(&b_hh[1536 + d]);
                float c_old = sh_c[rl * 32 + dl];
                float c = sigf(gf) * c_old + sigf(gi) * tanhf(gg);
                float h = sigf(go) * tanhf(c);
                sh_c[rl * 32 + dl] = c;
                sh_h[rl * 32 + dl] = h;
            }
        }
        __syncthreads();
        // coalesced write-out
        {
            int rl = tid >> 1, half = (tid & 1) * 16;
            int p = m0 + rl;
            int dg = (n0 >> 2) + half;
            float4* ch = (float4*)&sh_c[rl * 32 + half];
            float4* hh4 = (float4*)&sh_h[rl * 32 + half];
#pragma unroll
            for (int j = 0; j < 4; j++)
                *(float4*)&cbuf[(size_t)p * DD + dg + 4 * j] = ch[j];
            if (step == KS - 1) {
#pragma unroll
                for (int j = 0; j < 4; j++)
                    *(float4*)&out[(size_t)p * DD + dg + 4 * j] = hh4[j];
            } else {
                uint32_t hi[8], lo[8];
#pragma unroll
                for (int j = 0; j < 8; j++) {
                    float v0 = sh_h[rl * 32 + half + 2 * j];
                    float v1 = sh_h[rl * 32 + half + 2 * j + 1];
                    __nv_bfloat16 h0, l0, h1, l1;
                    split2(v0, h0, l0);
                    split2(v1, h1, l1);
                    hi[j] = pack_bf2(h0, h1);
                    lo[j] = pack_bf2(l0, l1);
                }
                size_t base = (size_t)p * K3D + dg;
                uint4 u0 = make_uint4(hi[0], hi[1], hi[2], hi[3]);
                uint4 u1 = make_uint4(hi[4], hi[5], hi[6], hi[7]);
                uint4 v0 = make_uint4(lo[0], lo[1], lo[2], lo[3]);
                uint4 v1 = make_uint4(lo[4], lo[5], lo[6], lo[7]);
                *(uint4*)&h3out[base] = u0;
                *(uint4*)&h3out[base + 8] = u1;
                *(uint4*)&h3out[base + 512] = u0;
                *(uint4*)&h3out[base + 520] = u1;
                *(uint4*)&h3out[base + 1024] = v0;
                *(uint4*)&h3out[base + 1032] = v1;
            }
        }
    }
}

// ---------------------------------------------------------------------------
// Elementwise / prep kernels
// ---------------------------------------------------------------------------
__global__ void glu3_kernel(const float* __restrict__ x) {
    int i = blockIdx.x * blockDim.x + threadIdx.x;
    if (i >= PP * DH) return;
    int p = i >> 8;
    int c = i & 255;
    float a = x[p * 512 + c];
    float b = x[p * 512 + 256 + c];
    float v = a * sigf(b);
    __nv_bfloat16 hi, lo;
    split2(v, hi, lo);
    size_t base = (size_t)p * K3H;
    g_glu3[base + c] = hi;
    g_glu3[base + 256 + c] = hi;
    g_glu3[base + 512 + c] = lo;
}

// STYLE 0: A-side [hi|hi|lo];  STYLE 1: B-side [hi|lo|hi].  ILV: row -> 4d+g.
template <int STYLE, bool ILV>
__global__ void wsplit_kernel(const float* __restrict__ w,
                              __nv_bfloat16* __restrict__ dst, int K, int total) {
    int i = blockIdx.x * blockDim.x + threadIdx.x;
    if (i >= total) return;
    int n = i / K;
    int k = i - n * K;
    int nd = ILV ? (((n & 511) << 2) + (n >> 9)) : n;
    __nv_bfloat16 hi, lo;
    split2(w[i], hi, lo);
    size_t base = (size_t)nd * 3 * K;
    if (STYLE == 0) {
        dst[base + k] = hi; dst[base + K + k] = hi; dst[base + 2 * K + k] = lo;
    } else {
        dst[base + k] = hi; dst[base + K + k] = lo; dst[base + 2 * K + k] = hi;
    }
}

// conv_w (512x256) -> g_cwT3[256][1536] B-style (transposed)
__global__ void wsplitT_kernel(const float* __restrict__ w) {
    int i = blockIdx.x * blockDim.x + threadIdx.x;
    if (i >= DD * DH) return;
    int d = i >> 8, c = i & 255;
    __nv_bfloat16 hi, lo;
    split2(w[i], hi, lo);
    size_t base = (size_t)c * K3D;
    g_cwT3[base + d] = hi;
    g_cwT3[base + 512 + d] = lo;
    g_cwT3[base + 1024 + d] = hi;
}

// fused bias: g_bf[n'] = b_ih[nsrc] + w_ih[nsrc,:] . conv_b
__global__ void bfvec_kernel(const float* __restrict__ w_ih,
                             const float* __restrict__ b_ih,
                             const float* __restrict__ conv_b) {
    int gid = blockIdx.x * blockDim.x + threadIdx.x;
    int warp = gid >> 5;
    int lane = gid & 31;
    if (warp >= G4) return;
    int nsrc = ((warp & 3) << 9) + (warp >> 2);
    float s = 0.f;
#pragma unroll 4
    for (int k = lane; k < DD; k += 32)
        s += w_ih[(size_t)nsrc * DD + k] * conv_b[k];
#pragma unroll
    for (int o = 16; o; o >>= 1) s += __shfl_xor_sync(0xFFFFFFFFu, s, o);
    if (!lane) g_bf[warp] = s + b_ih[nsrc];
}

// step 0 cell (h=0, c=0)
__global__ void cell0_kernel(const float* __restrict__ b_ih,
                             const float* __restrict__ b_hh,
                             __nv_bfloat16* __restrict__ h3out) {
    int i = blockIdx.x * blockDim.x + threadIdx.x;
    if (i >= PP * DD) return;
    int p = i >> 9, d = i & 511, l = p & 511;
    float4 q;
    if (l - 8 >= 0) {
        q = *(const float4*)&g_gx[(size_t)(p - 8) * G4 + 4 * d];
    } else {
        q.x = b_ih[d]; q.y = b_ih[512 + d];
        q.z = b_ih[1024 + d]; q.w = b_ih[1536 + d];
    }
    float gi = q.x + b_hh[d];
    float gg = q.z + b_hh[1024 + d];
    float go = q.w + b_hh[1536 + d];
    float c = sigf(gi) * tanhf(gg);
    float h = sigf(go) * tanhf(c);
    g_c[i] = c;
    __nv_bfloat16 hi, lo;
    split2(h, hi, lo);
    size_t base = (size_t)p * K3D;
    h3out[base + d] = hi;
    h3out[base + 512 + d] = hi;
    h3out[base + 1024 + d] = lo;
}

// ---------------------------------------------------------------------------
// Launch
// ---------------------------------------------------------------------------
extern "C" void kernel_launch(void* const* d_in, const int* in_sizes, int n_in,
                              void* d_out, int out_size) {
    const float* x      = (const float*)d_in[0];
    const float* conv_w = (const float*)d_in[1];
    const float* conv_b = (const float*)d_in[2];
    const float* w_ih   = (const float*)d_in[3];
    const float* w_hh   = (const float*)d_in[4];
    const float* b_ih   = (const float*)d_in[5];
    const float* b_hh   = (const float*)d_in[6];
    float* out = (float*)d_out;

    __nv_bfloat16 *p_glu3, *p_h3a, *p_h3b, *p_wih3, *p_whh3, *p_cwT3, *p_wf3;
    float *p_gx, *p_c, *p_wf, *p_bf;
    cudaGetSymbolAddress((void**)&p_glu3, g_glu3);
    cudaGetSymbolAddress((void**)&p_gx, g_gx);
    cudaGetSymbolAddress((void**)&p_h3a, g_h3a);
    cudaGetSymbolAddress((void**)&p_h3b, g_h3b);
    cudaGetSymbolAddress((void**)&p_c, g_c);
    cudaGetSymbolAddress((void**)&p_wih3, g_wih3);
    cudaGetSymbolAddress((void**)&p_whh3, g_whh3);
    cudaGetSymbolAddress((void**)&p_cwT3, g_cwT3);
    cudaGetSymbolAddress((void**)&p_wf, g_wf);
    cudaGetSymbolAddress((void**)&p_wf3, g_wf3);
    cudaGetSymbolAddress((void**)&p_bf, g_bf);

    cudaFuncSetAttribute(gemm_mma<K3D, DH, false, 0>,
                         cudaFuncAttributeMaxDynamicSharedMemorySize, SMEM_BYTES);
    cudaFuncSetAttribute(gemm_mma<K3H, G4, true, 0>,
                         cudaFuncAttributeMaxDynamicSharedMemorySize, SMEM_BYTES);
    cudaFuncSetAttribute(gemm_mma<K3D, G4, false, 1>,
                         cudaFuncAttributeMaxDynamicSharedMemorySize, SMEM_BYTES);

    // 1) input prep
    glu3_kernel<<<(PP * DH + 255) / 256, 256>>>(x);
    wsplit_kernel<0, true><<<(G4 * DD + 255) / 256, 256>>>(w_ih, p_wih3, DD, G4 * DD);
    wsplit_kernel<1, true><<<(G4 * DD + 255) / 256, 256>>>(w_hh, p_whh3, DD, G4 * DD);
    wsplitT_kernel<<<(DD * DH + 255) / 256, 256>>>(conv_w);
    bfvec_kernel<<<(G4 * 32 + 255) / 256, 256>>>(w_ih, b_ih, conv_b);

    // 2) Wf = w_ih @ conv_w  (2048 x 256, K'=1536), rows gate-interleaved
    gemm_mma<K3D, DH, false, 0><<<dim3(DH / 128, G4 / 128), 256, SMEM_BYTES>>>(
        p_wih3, p_cwT3, nullptr, p_wf,
        nullptr, nullptr, nullptr, nullptr, nullptr, nullptr, 0);
    wsplit_kernel<1, false><<<(G4 * DH + 255) / 256, 256>>>(p_wf, p_wf3, DH, G4 * DH);

    // 3) Gx = glu @ Wf^T + bf  (8192 x 2048, K'=768), gate-interleaved output
    gemm_mma<K3H, G4, true, 0><<<dim3(G4 / 128, PP / 128), 256, SMEM_BYTES>>>(
        p_glu3, p_wf3, p_bf, p_gx,
        nullptr, nullptr, nullptr, nullptr, nullptr, nullptr, 0);

    // 4) step 0
    cell0_kernel<<<(PP * DD + 255) / 256, 256>>>(b_ih, b_hh, p_h3a);

    // 5) steps 1..8: recurrent GEMM with fused cell epilogue (ping-pong h3)
    __nv_bfloat16* hping[2] = {p_h3a, p_h3b};
    for (int step = 1; step < KS; step++) {
        const __nv_bfloat16* h_in = hping[(step - 1) & 1];
        __nv_bfloat16* h_out = hping[step & 1];
        gemm_mma<K3D, G4, false, 1><<<dim3(G4 / 128, PP / 128), 256, SMEM_BYTES>>>(
            h_in, p_whh3, nullptr, nullptr,
            p_gx, b_ih, b_hh, p_c, h_out, out, step);
    }
}

// round 6
// speedup vs baseline: 3.5071x; 1.3061x over previous
#include <cuda_runtime.h>
#include <cuda_bf16.h>
#include <cuda_fp16.h>
#include <math.h>
#include <stdint.h>

// Problem constants
#define BB 16
#define LL 512
#define DD 512
#define DH 256
#define G4 2048
#define PP (BB*LL)      // 8192
#define KS 9
#define K3D (3*DD)      // 1536 (bf16 3-split, Wf GEMM only)
#define K2D (2*DD)      // 1024 (fp16 2-split, recurrent)
#define K2H (2*DH)      // 512  (fp16 2-split, Gx)

// ---------------------------------------------------------------------------
// Scratch
// ---------------------------------------------------------------------------
__device__ __half         g_glu2[(size_t)PP * K2H];    //  8MB  A' of Gx GEMM
__device__ float          g_gx[(size_t)PP * G4];       // 64MB  gate-interleaved (pre-bias-fused)
__device__ __half         g_h2a[(size_t)PP * K2D];     // 16MB  h split, ping
__device__ __half         g_h2b[(size_t)PP * K2D];     // 16MB  h split, pong
__device__ float          g_c[(size_t)PP * DD];        // 16MB  cell state
__device__ __nv_bfloat16  g_wih3[(size_t)G4 * K3D];    //  6MB  A' of Wf GEMM (interleaved rows)
__device__ __half         g_whh2[(size_t)G4 * K2D];    //  4MB  B' of recurrent GEMM (interleaved)
__device__ __nv_bfloat16  g_cwT3[(size_t)DH * K3D];    //  .75MB B' of Wf GEMM
__device__ float          g_wf[(size_t)G4 * DH];       //  2MB  Wf = w_ih @ conv_w (fp32)
__device__ __half         g_wf2[(size_t)G4 * K2H];     //  2MB  B' of Gx GEMM
__device__ float          g_bf[G4];                    //  8KB  fused bias (interleaved)

// ---------------------------------------------------------------------------
// helpers
// ---------------------------------------------------------------------------
__device__ __forceinline__ uint32_t s2u(const void* p) {
    uint32_t a;
    asm("{ .reg .u64 t; cvta.to.shared.u64 t, %1; cvt.u32.u64 %0, t; }"
        : "=r"(a) : "l"(p));
    return a;
}
__device__ __forceinline__ float sigf(float x) { return 1.0f / (1.0f + expf(-x)); }
__device__ __forceinline__ void split2b(float v, __nv_bfloat16& hi, __nv_bfloat16& lo) {
    hi = __float2bfloat16_rn(v);
    lo = __float2bfloat16_rn(v - __bfloat162float(hi));
}
__device__ __forceinline__ void split2h(float v, __half& hi, __half& lo) {
    hi = __float2half_rn(v);
    lo = __float2half_rn(v - __half2float(hi));
}
__device__ __forceinline__ uint32_t pack_h2(__half a, __half b) {
    __half2 t = __halves2half2(a, b);
    return *(uint32_t*)&t;
}

#define LDSM4(r0, r1, r2, r3, addr)                                            \
    asm volatile("ldmatrix.sync.aligned.m8n8.x4.shared.b16 {%0,%1,%2,%3}, [%4];" \
                 : "=r"(r0), "=r"(r1), "=r"(r2), "=r"(r3) : "r"(addr))

__device__ __forceinline__ void mma_bf16(float* c, const uint32_t* a, uint32_t b0, uint32_t b1) {
    asm volatile("mma.sync.aligned.m16n8k16.row.col.f32.bf16.bf16.f32 "
                 "{%0,%1,%2,%3},{%4,%5,%6,%7},{%8,%9},{%0,%1,%2,%3};"
                 : "+f"(c[0]), "+f"(c[1]), "+f"(c[2]), "+f"(c[3])
                 : "r"(a[0]), "r"(a[1]), "r"(a[2]), "r"(a[3]), "r"(b0), "r"(b1));
}
__device__ __forceinline__ void mma_f16(float* c, const uint32_t* a, uint32_t b0, uint32_t b1) {
    asm volatile("mma.sync.aligned.m16n8k16.row.col.f32.f16.f16.f32 "
                 "{%0,%1,%2,%3},{%4,%5,%6,%7},{%8,%9},{%0,%1,%2,%3};"
                 : "+f"(c[0]), "+f"(c[1]), "+f"(c[2]), "+f"(c[3])
                 : "r"(a[0]), "r"(a[1]), "r"(a[2]), "r"(a[3]), "r"(b0), "r"(b1));
}

#define CPASYNC16(dst, src)                                                    \
    asm volatile("cp.async.cg.shared.global [%0], [%1], 16;" :: "r"(dst), "l"(src))
#define CPCOMMIT() asm volatile("cp.async.commit_group;" ::: "memory")
#define CPWAIT(n)  asm volatile("cp.async.wait_group %0;" :: "n"(n) : "memory")

// ---------------------------------------------------------------------------
// 16-bit mma.sync GEMM, CTA 128x128, BK=64, 3-stage cp.async.
// T: element type (__half / __nv_bfloat16). EPI=0: store (+bias). EPI=1: cell.
// ---------------------------------------------------------------------------
#define STAGE_BYTES 32768
#define SMEM_BYTES (3 * STAGE_BYTES)

template <typename T, int KT, int NTOT, bool BIAS, int EPI>
__global__ void __launch_bounds__(256, 2)
gemm_mma(const T* __restrict__ A,
         const T* __restrict__ B,
         const float* __restrict__ bias,
         float* __restrict__ C,
         const float* __restrict__ gx,
         const float* __restrict__ b_ih,
         const float* __restrict__ b_hh,
         float* __restrict__ cbuf,
         __half* __restrict__ h2out,
         float* __restrict__ out,
         int step) {
    extern __shared__ char smem[];
    const uint32_t sb = s2u(smem);
    const int tid = threadIdx.x;
    const int wid = tid >> 5;
    const int lane = tid & 31;
    const int m0 = blockIdx.y * 128;
    const int n0 = blockIdx.x * 128;
    const int wm = (wid >> 1) * 32;
    const int wn = (wid & 1) * 64;

    constexpr int NKC = KT / 64;

    const int lrow8 = tid >> 3;
    const int lc = (tid & 7) * 16;

    auto load_stage = [&](int kc, int s) {
        uint32_t sA = sb + s * STAGE_BYTES;
        uint32_t sB = sA + 16384;
        int k0 = kc * 64;
#pragma unroll
        for (int t = 0; t < 4; t++) {
            int row = lrow8 + t * 32;
            uint32_t swz = (uint32_t)((row & 7) << 4);
            uint32_t off = (uint32_t)(row * 128) + ((uint32_t)lc ^ swz);
            CPASYNC16(sA + off, A + (size_t)(m0 + row) * KT + k0 + (lc >> 1));
            CPASYNC16(sB + off, B + (size_t)(n0 + row) * KT + k0 + (lc >> 1));
        }
    };

    load_stage(0, 0); CPCOMMIT();
    load_stage(1, 1); CPCOMMIT();

    float acc[2][8][4];
#pragma unroll
    for (int i = 0; i < 2; i++)
#pragma unroll
        for (int j = 0; j < 8; j++)
#pragma unroll
            for (int q = 0; q < 4; q++) acc[i][j][q] = 0.0f;

    const int lr16 = lane & 15;
    const uint32_t lhi = (uint32_t)((lane >> 4) * 16);
    const uint32_t lswz = (uint32_t)((lr16 & 7) << 4);

#pragma unroll 1
    for (int kc = 0; kc < NKC; kc++) {
        __syncthreads();
        if (kc + 2 < NKC) {
            load_stage(kc + 2, (kc + 2) % 3);
            CPCOMMIT();
            CPWAIT(2);
        } else if (kc + 1 < NKC) {
            CPWAIT(1);
        } else {
            CPWAIT(0);
        }
        __syncthreads();

        uint32_t sA = sb + (kc % 3) * STAGE_BYTES;
        uint32_t sB = sA + 16384;

#pragma unroll
        for (int k16 = 0; k16 < 4; k16++) {
            uint32_t colb = ((uint32_t)(k16 * 32) + lhi) ^ lswz;
            uint32_t a[2][4];
#pragma unroll
            for (int mt = 0; mt < 2; mt++) {
                uint32_t addr = sA + (uint32_t)((wm + mt * 16 + lr16) * 128) + colb;
                LDSM4(a[mt][0], a[mt][1], a[mt][2], a[mt][3], addr);
            }
            uint32_t br[4][4];
#pragma unroll
            for (int g = 0; g < 4; g++) {
                uint32_t addr = sB + (uint32_t)((wn + g * 16 + lr16) * 128) + colb;
                LDSM4(br[g][0], br[g][1], br[g][2], br[g][3], addr);
            }
#pragma unroll
            for (int mt = 0; mt < 2; mt++)
#pragma unroll
                for (int g = 0; g < 4; g++) {
                    if constexpr (sizeof(T) == 2 && __is_same(T, __half)) {
                        mma_f16(acc[mt][2 * g + 0], a[mt], br[g][0], br[g][2]);
                        mma_f16(acc[mt][2 * g + 1], a[mt], br[g][1], br[g][3]);
                    } else {
                        mma_bf16(acc[mt][2 * g + 0], a[mt], br[g][0], br[g][2]);
                        mma_bf16(acc[mt][2 * g + 1], a[mt], br[g][1], br[g][3]);
                    }
                }
        }
    }

    if constexpr (EPI == 0) {
        const int qrow = lane >> 2;
        const int qcol = (lane & 3) * 2;
#pragma unroll
        for (int mt = 0; mt < 2; mt++) {
#pragma unroll
            for (int nt = 0; nt < 8; nt++) {
                int row = m0 + wm + mt * 16 + qrow;
                int col = n0 + wn + nt * 8 + qcol;
                float bx = 0.f, by = 0.f;
                if (BIAS) { bx = __ldg(&bias[col]); by = __ldg(&bias[col + 1]); }
                float2 v0 = make_float2(acc[mt][nt][0] + bx, acc[mt][nt][1] + by);
                float2 v1 = make_float2(acc[mt][nt][2] + bx, acc[mt][nt][3] + by);
                *(float2*)&C[(size_t)row * NTOT + col] = v0;
                *(float2*)&C[(size_t)(row + 8) * NTOT + col] = v1;
            }
        }
    } else {
        // -------- fused LSTM cell epilogue --------
        float* sh_h = (float*)smem;                 // [128][32]
        float* sh_c = (float*)(smem + 16384);       // [128][32]
        __syncthreads();
        {
            int rl = tid >> 1, half = (tid & 1) * 16;
            const float4* src = (const float4*)&cbuf[(size_t)(m0 + rl) * DD + (n0 >> 2) + half];
            float4* dst = (float4*)&sh_c[rl * 32 + half];
#pragma unroll
            for (int j = 0; j < 4; j++) dst[j] = src[j];
        }
        __syncthreads();

        const int qrow = lane >> 2;
        const bool odd = lane & 1;
#pragma unroll
        for (int mt = 0; mt < 2; mt++) {
#pragma unroll
            for (int nt = 0; nt < 8; nt++) {
                float* a = acc[mt][nt];
                float e0 = __shfl_xor_sync(0xFFFFFFFFu, a[0], 1);
                float e1 = __shfl_xor_sync(0xFFFFFFFFu, a[1], 1);
                float e2 = __shfl_xor_sync(0xFFFFFFFFu, a[2], 1);
                float e3 = __shfl_xor_sync(0xFFFFFFFFu, a[3], 1);
                float gi, gf, gg, go;
                if (!odd) { gi = a[0]; gf = a[1]; gg = e0; go = e1; }
                else      { gi = e2;   gf = e3;   gg = a[2]; go = a[3]; }
                int rl = wm + mt * 16 + qrow + (odd ? 8 : 0);
                int dl = (wn >> 2) + nt * 2 + ((lane & 3) >> 1);
                int p = m0 + rl;
                int d = (n0 >> 2) + dl;
                int l = p & 511;
                float4 q;
                if (l + step - 8 >= 0) {
                    q = *(const float4*)&gx[(size_t)(p + step - 8) * G4 + 4 * d];
                } else {
                    q.x = __ldg(&b_ih[d]);
                    q.y = __ldg(&b_ih[512 + d]);
                    q.z = __ldg(&b_ih[1024 + d]);
                    q.w = __ldg(&b_ih[1536 + d]);
                }
                gi += q.x + __ldg(&b_hh[d]);
                gf += q.y + __ldg(&b_hh[512 + d]);
                gg += q.z + __ldg(&b_hh[1024 + d]);
                go += q.w + __ldg(&b_hh[1536 + d]);
                float c_old = sh_c[rl * 32 + dl];
                float c = sigf(gf) * c_old + sigf(gi) * tanhf(gg);
                float h = sigf(go) * tanhf(c);
                sh_c[rl * 32 + dl] = c;
                sh_h[rl * 32 + dl] = h;
            }
        }
        __syncthreads();
        {
            int rl = tid >> 1, half = (tid & 1) * 16;
            int p = m0 + rl;
            int dg = (n0 >> 2) + half;
            float4* ch = (float4*)&sh_c[rl * 32 + half];
            float4* hh4 = (float4*)&sh_h[rl * 32 + half];
#pragma unroll
            for (int j = 0; j < 4; j++)
                *(float4*)&cbuf[(size_t)p * DD + dg + 4 * j] = ch[j];
            if (step == KS - 1) {
#pragma unroll
                for (int j = 0; j < 4; j++)
                    *(float4*)&out[(size_t)p * DD + dg + 4 * j] = hh4[j];
            } else {
                uint32_t hi[8], lo[8];
#pragma unroll
                for (int j = 0; j < 8; j++) {
                    float v0 = sh_h[rl * 32 + half + 2 * j];
                    float v1 = sh_h[rl * 32 + half + 2 * j + 1];
                    __half h0, l0, h1, l1;
                    split2h(v0, h0, l0);
                    split2h(v1, h1, l1);
                    hi[j] = pack_h2(h0, h1);
                    lo[j] = pack_h2(l0, l1);
                }
                size_t base = (size_t)p * K2D + dg;
                *(uint4*)&h2out[base]           = make_uint4(hi[0], hi[1], hi[2], hi[3]);
                *(uint4*)&h2out[base + 8]       = make_uint4(hi[4], hi[5], hi[6], hi[7]);
                *(uint4*)&h2out[base + 512]     = make_uint4(lo[0], lo[1], lo[2], lo[3]);
                *(uint4*)&h2out[base + 512 + 8] = make_uint4(lo[4], lo[5], lo[6], lo[7]);
            }
        }
    }
}

// ---------------------------------------------------------------------------
// Elementwise / prep kernels
// ---------------------------------------------------------------------------
// GLU + fp16 hi/lo split -> g_glu2 = [gh(256) | gl(256)]
__global__ void glu2_kernel(const float* __restrict__ x) {
    int i = blockIdx.x * blockDim.x + threadIdx.x;
    if (i >= PP * DH) return;
    int p = i >> 8;
    int c = i & 255;
    float a = x[p * 512 + c];
    float b = x[p * 512 + 256 + c];
    float v = a * sigf(b);
    __half hi, lo;
    split2h(v, hi, lo);
    size_t base = (size_t)p * K2H;
    g_glu2[base + c] = hi;
    g_glu2[base + 256 + c] = lo;
}

// bf16 3-split A-style [hi|hi|lo] with gate interleave (Wf GEMM A operand)
__global__ void wsplit3a_kernel(const float* __restrict__ w,
                                __nv_bfloat16* __restrict__ dst, int K, int total) {
    int i = blockIdx.x * blockDim.x + threadIdx.x;
    if (i >= total) return;
    int n = i / K;
    int k = i - n * K;
    int nd = ((n & 511) << 2) + (n >> 9);
    __nv_bfloat16 hi, lo;
    split2b(w[i], hi, lo);
    size_t base = (size_t)nd * 3 * K;
    dst[base + k] = hi; dst[base + K + k] = hi; dst[base + 2 * K + k] = lo;
}

// fp16 B-style [hi|hi] (single-rounded weight, duplicated). ILV optional.
template <bool ILV>
__global__ void wsplit2_kernel(const float* __restrict__ w,
                               __half* __restrict__ dst, int K, int total) {
    int i = blockIdx.x * blockDim.x + threadIdx.x;
    if (i >= total) return;
    int n = i / K;
    int k = i - n * K;
    int nd = ILV ? (((n & 511) << 2) + (n >> 9)) : n;
    __half hi = __float2half_rn(w[i]);
    size_t base = (size_t)nd * 2 * K;
    dst[base + k] = hi;
    dst[base + K + k] = hi;
}

// conv_w (512x256) -> g_cwT3[256][1536] bf16 B-style (transposed)
__global__ void wsplitT_kernel(const float* __restrict__ w) {
    int i = blockIdx.x * blockDim.x + threadIdx.x;
    if (i >= DD * DH) return;
    int d = i >> 8, c = i & 255;
    __nv_bfloat16 hi, lo;
    split2b(w[i], hi, lo);
    size_t base = (size_t)c * K3D;
    g_cwT3[base + d] = hi;
    g_cwT3[base + 512 + d] = lo;
    g_cwT3[base + 1024 + d] = hi;
}

// fused bias: g_bf[n'] = b_ih[nsrc] + w_ih[nsrc,:] . conv_b
__global__ void bfvec_kernel(const float* __restrict__ w_ih,
                             const float* __restrict__ b_ih,
                             const float* __restrict__ conv_b) {
    int gid = blockIdx.x * blockDim.x + threadIdx.x;
    int warp = gid >> 5;
    int lane = gid & 31;
    if (warp >= G4) return;
    int nsrc = ((warp & 3) << 9) + (warp >> 2);
    float s = 0.f;
#pragma unroll 4
    for (int k = lane; k < DD; k += 32)
        s += w_ih[(size_t)nsrc * DD + k] * conv_b[k];
#pragma unroll
    for (int o = 16; o; o >>= 1) s += __shfl_xor_sync(0xFFFFFFFFu, s, o);
    if (!lane) g_bf[warp] = s + b_ih[nsrc];
}

// step 0 cell (h=0, c=0); writes fp16 hi/lo h
__global__ void cell0_kernel(const float* __restrict__ b_ih,
                             const float* __restrict__ b_hh,
                             __half* __restrict__ h2out) {
    int i = blockIdx.x * blockDim.x + threadIdx.x;
    if (i >= PP * DD) return;
    int p = i >> 9, d = i & 511, l = p & 511;
    float4 q;
    if (l - 8 >= 0) {
        q = *(const float4*)&g_gx[(size_t)(p - 8) * G4 + 4 * d];
    } else {
        q.x = b_ih[d]; q.y = b_ih[512 + d];
        q.z = b_ih[1024 + d]; q.w = b_ih[1536 + d];
    }
    float gi = q.x + b_hh[d];
    float gg = q.z + b_hh[1024 + d];
    float go = q.w + b_hh[1536 + d];
    float c = sigf(gi) * tanhf(gg);
    float h = sigf(go) * tanhf(c);
    g_c[i] = c;
    __half hi, lo;
    split2h(h, hi, lo);
    size_t base = (size_t)p * K2D;
    h2out[base + d] = hi;
    h2out[base + 512 + d] = lo;
}

// ---------------------------------------------------------------------------
// Launch
// ---------------------------------------------------------------------------
extern "C" void kernel_launch(void* const* d_in, const int* in_sizes, int n_in,
                              void* d_out, int out_size) {
    const float* x      = (const float*)d_in[0];
    const float* conv_w = (const float*)d_in[1];
    const float* conv_b = (const float*)d_in[2];
    const float* w_ih   = (const float*)d_in[3];
    const float* w_hh   = (const float*)d_in[4];
    const float* b_ih   = (const float*)d_in[5];
    const float* b_hh   = (const float*)d_in[6];
    float* out = (float*)d_out;

    __nv_bfloat16 *p_wih3, *p_cwT3;
    __half *p_glu2, *p_h2a, *p_h2b, *p_whh2, *p_wf2;
    float *p_gx, *p_c, *p_wf, *p_bf;
    cudaGetSymbolAddress((void**)&p_glu2, g_glu2);
    cudaGetSymbolAddress((void**)&p_gx, g_gx);
    cudaGetSymbolAddress((void**)&p_h2a, g_h2a);
    cudaGetSymbolAddress((void**)&p_h2b, g_h2b);
    cudaGetSymbolAddress((void**)&p_c, g_c);
    cudaGetSymbolAddress((void**)&p_wih3, g_wih3);
    cudaGetSymbolAddress((void**)&p_whh2, g_whh2);
    cudaGetSymbolAddress((void**)&p_cwT3, g_cwT3);
    cudaGetSymbolAddress((void**)&p_wf, g_wf);
    cudaGetSymbolAddress((void**)&p_wf2, g_wf2);
    cudaGetSymbolAddress((void**)&p_bf, g_bf);

    cudaFuncSetAttribute(gemm_mma<__nv_bfloat16, K3D, DH, false, 0>,
                         cudaFuncAttributeMaxDynamicSharedMemorySize, SMEM_BYTES);
    cudaFuncSetAttribute(gemm_mma<__half, K2H, G4, true, 0>,
                         cudaFuncAttributeMaxDynamicSharedMemorySize, SMEM_BYTES);
    cudaFuncSetAttribute(gemm_mma<__half, K2D, G4, false, 1>,
                         cudaFuncAttributeMaxDynamicSharedMemorySize, SMEM_BYTES);

    // 1) input prep
    glu2_kernel<<<(PP * DH + 255) / 256, 256>>>(x);
    wsplit3a_kernel<<<(G4 * DD + 255) / 256, 256>>>(w_ih, p_wih3, DD, G4 * DD);
    wsplit2_kernel<true><<<(G4 * DD + 255) / 256, 256>>>(w_hh, p_whh2, DD, G4 * DD);
    wsplitT_kernel<<<(DD * DH + 255) / 256, 256>>>(conv_w);
    bfvec_kernel<<<(G4 * 32 + 255) / 256, 256>>>(w_ih, b_ih, conv_b);

    // 2) Wf = w_ih @ conv_w (bf16 3-split, high accuracy), rows gate-interleaved
    gemm_mma<__nv_bfloat16, K3D, DH, false, 0><<<dim3(DH / 128, G4 / 128), 256, SMEM_BYTES>>>(
        p_wih3, p_cwT3, nullptr, p_wf,
        nullptr, nullptr, nullptr, nullptr, nullptr, nullptr, 0);
    wsplit2_kernel<false><<<(G4 * DH + 255) / 256, 256>>>(p_wf, p_wf2, DH, G4 * DH);

    // 3) Gx = glu @ Wf^T + bf  (fp16 2-split, K'=512), gate-interleaved output
    gemm_mma<__half, K2H, G4, true, 0><<<dim3(G4 / 128, PP / 128), 256, SMEM_BYTES>>>(
        p_glu2, p_wf2, p_bf, p_gx,
        nullptr, nullptr, nullptr, nullptr, nullptr, nullptr, 0);

    // 4) step 0
    cell0_kernel<<<(PP * DD + 255) / 256, 256>>>(b_ih, b_hh, p_h2a);

    // 5) steps 1..8: recurrent GEMM (fp16 2-split, K'=1024) + fused cell
    __half* hping[2] = {p_h2a, p_h2b};
    for (int step = 1; step < KS; step++) {
        const __half* h_in = hping[(step - 1) & 1];
        __half* h_out = hping[step & 1];
        gemm_mma<__half, K2D, G4, false, 1><<<dim3(G4 / 128, PP / 128), 256, SMEM_BYTES>>>(
            h_in, p_whh2, nullptr, nullptr,
            p_gx, b_ih, b_hh, p_c, h_out, out, step);
    }
}

// round 13
// speedup vs baseline: 4.9059x; 1.3988x over previous
#include <cuda_runtime.h>
#include <cuda_bf16.h>
#include <cuda_fp16.h>
#include <math.h>
#include <stdint.h>

// Problem constants
#define BB 16
#define LL 512
#define DD 512
#define DH 256
#define G4 2048
#define PP (BB*LL)      // 8192
#define KS 9
#define K3D (3*DD)      // 1536 (bf16 3-split, Wf GEMM only)
#define K2H (2*DH)      // 512  (fp16 2-split, Gx GEMM)

// ---------------------------------------------------------------------------
// Scratch
// ---------------------------------------------------------------------------
__device__ __half         g_glu2[(size_t)PP * K2H];    //  8MB  A' of Gx GEMM (exact 2-split)
__device__ float          g_gx[(size_t)PP * G4];       // 64MB  gate-interleaved, all biases folded
__device__ __half         g_h1a[(size_t)PP * DD];      //  8MB  h fp16, ping
__device__ __half         g_h1b[(size_t)PP * DD];      //  8MB  h fp16, pong
__device__ float          g_c[(size_t)PP * DD];        // 16MB  cell state
__device__ __nv_bfloat16  g_wih3[(size_t)G4 * K3D];    //  6MB  A' of Wf GEMM (interleaved rows)
__device__ __half         g_whh1[(size_t)G4 * DD];     //  2MB  w_hh fp16 (interleaved rows)
__device__ __nv_bfloat16  g_cwT3[(size_t)DH * K3D];    //  .75MB B' of Wf GEMM
__device__ float          g_wf[(size_t)G4 * DH];       //  2MB  Wf = w_ih @ conv_w (fp32)
__device__ __half         g_wf2[(size_t)G4 * K2H];     //  2MB  B' of Gx GEMM [hi|hi]
__device__ float          g_bf[G4];                    //  8KB  Gx bias: b_ih + w_ih.conv_b + b_hh
__device__ float          g_b0[G4];                    //  8KB  b_ih + b_hh (interleaved)

// ---------------------------------------------------------------------------
// helpers
// ---------------------------------------------------------------------------
__device__ __forceinline__ uint32_t s2u(const void* p) {
    uint32_t a;
    asm("{ .reg .u64 t; cvta.to.shared.u64 t, %1; cvt.u32.u64 %0, t; }"
        : "=r"(a) : "l"(p));
    return a;
}
__device__ __forceinline__ float sigf(float x) { return 1.0f / (1.0f + expf(-x)); }
__device__ __forceinline__ void split2b(float v, __nv_bfloat16& hi, __nv_bfloat16& lo) {
    hi = __float2bfloat16_rn(v);
    lo = __float2bfloat16_rn(v - __bfloat162float(hi));
}
__device__ __forceinline__ void split2h(float v, __half& hi, __half& lo) {
    hi = __float2half_rn(v);
    lo = __float2half_rn(v - __half2float(hi));
}
__device__ __forceinline__ uint32_t pack_h2(__half a, __half b) {
    __half2 t = __halves2half2(a, b);
    return *(uint32_t*)&t;
}

#define LDSM4(r0, r1, r2, r3, addr)                                            \
    asm volatile("ldmatrix.sync.aligned.m8n8.x4.shared.b16 {%0,%1,%2,%3}, [%4];" \
                 : "=r"(r0), "=r"(r1), "=r"(r2), "=r"(r3) : "r"(addr))

__device__ __forceinline__ void mma_bf16(float* c, const uint32_t* a, uint32_t b0, uint32_t b1) {
    asm volatile("mma.sync.aligned.m16n8k16.row.col.f32.bf16.bf16.f32 "
                 "{%0,%1,%2,%3},{%4,%5,%6,%7},{%8,%9},{%0,%1,%2,%3};"
                 : "+f"(c[0]), "+f"(c[1]), "+f"(c[2]), "+f"(c[3])
                 : "r"(a[0]), "r"(a[1]), "r"(a[2]), "r"(a[3]), "r"(b0), "r"(b1));
}
__device__ __forceinline__ void mma_f16(float* c, const uint32_t* a, uint32_t b0, uint32_t b1) {
    asm volatile("mma.sync.aligned.m16n8k16.row.col.f32.f16.f16.f32 "
                 "{%0,%1,%2,%3},{%4,%5,%6,%7},{%8,%9},{%0,%1,%2,%3};"
                 : "+f"(c[0]), "+f"(c[1]), "+f"(c[2]), "+f"(c[3])
                 : "r"(a[0]), "r"(a[1]), "r"(a[2]), "r"(a[3]), "r"(b0), "r"(b1));
}

#define CPASYNC16(dst, src)                                                    \
    asm volatile("cp.async.cg.shared.global [%0], [%1], 16;" :: "r"(dst), "l"(src))
#define CPCOMMIT() asm volatile("cp.async.commit_group;" ::: "memory")
#define CPWAIT(n)  asm volatile("cp.async.wait_group %0;" :: "n"(n) : "memory")

// ---------------------------------------------------------------------------
// 16-bit mma.sync GEMM, CTA 128x128, BK=64, 3-stage cp.async.
// EPI=0: store (+bias).  EPI=1: fused LSTM cell epilogue (fp16 h out).
// ---------------------------------------------------------------------------
#define STAGE_BYTES 32768
#define SMEM_BYTES (3 * STAGE_BYTES)

template <typename T, int KT, int NTOT, bool BIAS, int EPI>
__global__ void __launch_bounds__(256, 2)
gemm_mma(const T* __restrict__ A,
         const T* __restrict__ B,
         const float* __restrict__ bias,
         float* __restrict__ C,
         const float* __restrict__ gx,
         const float* __restrict__ b0,
         float* __restrict__ cbuf,
         __half* __restrict__ h1out,
         float* __restrict__ out,
         int step) {
    extern __shared__ char smem[];
    const uint32_t sb = s2u(smem);
    const int tid = threadIdx.x;
    const int wid = tid >> 5;
    const int lane = tid & 31;
    const int m0 = blockIdx.y * 128;
    const int n0 = blockIdx.x * 128;
    const int wm = (wid >> 1) * 32;
    const int wn = (wid & 1) * 64;

    constexpr int NKC = KT / 64;

    const int lrow8 = tid >> 3;
    const int lc = (tid & 7) * 16;

    auto load_stage = [&](int kc, int s) {
        uint32_t sA = sb + s * STAGE_BYTES;
        uint32_t sB = sA + 16384;
        int k0 = kc * 64;
#pragma unroll
        for (int t = 0; t < 4; t++) {
            int row = lrow8 + t * 32;
            uint32_t swz = (uint32_t)((row & 7) << 4);
            uint32_t off = (uint32_t)(row * 128) + ((uint32_t)lc ^ swz);
            CPASYNC16(sA + off, A + (size_t)(m0 + row) * KT + k0 + (lc >> 1));
            CPASYNC16(sB + off, B + (size_t)(n0 + row) * KT + k0 + (lc >> 1));
        }
    };

    load_stage(0, 0); CPCOMMIT();
    load_stage(1, 1); CPCOMMIT();

    float acc[2][8][4];
#pragma unroll
    for (int i = 0; i < 2; i++)
#pragma unroll
        for (int j = 0; j < 8; j++)
#pragma unroll
            for (int q = 0; q < 4; q++) acc[i][j][q] = 0.0f;

    const int lr16 = lane & 15;
    const uint32_t lhi = (uint32_t)((lane >> 4) * 16);
    const uint32_t lswz = (uint32_t)((lr16 & 7) << 4);

#pragma unroll 1
    for (int kc = 0; kc < NKC; kc++) {
        __syncthreads();
        if (kc + 2 < NKC) {
            load_stage(kc + 2, (kc + 2) % 3);
            CPCOMMIT();
            CPWAIT(2);
        } else if (kc + 1 < NKC) {
            CPWAIT(1);
        } else {
            CPWAIT(0);
        }
        __syncthreads();

        uint32_t sA = sb + (kc % 3) * STAGE_BYTES;
        uint32_t sB = sA + 16384;

#pragma unroll
        for (int k16 = 0; k16 < 4; k16++) {
            uint32_t colb = ((uint32_t)(k16 * 32) + lhi) ^ lswz;
            uint32_t a[2][4];
#pragma unroll
            for (int mt = 0; mt < 2; mt++) {
                uint32_t addr = sA + (uint32_t)((wm + mt * 16 + lr16) * 128) + colb;
                LDSM4(a[mt][0], a[mt][1], a[mt][2], a[mt][3], addr);
            }
            uint32_t br[4][4];
#pragma unroll
            for (int g = 0; g < 4; g++) {
                uint32_t addr = sB + (uint32_t)((wn + g * 16 + lr16) * 128) + colb;
                LDSM4(br[g][0], br[g][1], br[g][2], br[g][3], addr);
            }
#pragma unroll
            for (int mt = 0; mt < 2; mt++)
#pragma unroll
                for (int g = 0; g < 4; g++) {
                    if constexpr (__is_same(T, __half)) {
                        mma_f16(acc[mt][2 * g + 0], a[mt], br[g][0], br[g][2]);
                        mma_f16(acc[mt][2 * g + 1], a[mt], br[g][1], br[g][3]);
                    } else {
                        mma_bf16(acc[mt][2 * g + 0], a[mt], br[g][0], br[g][2]);
                        mma_bf16(acc[mt][2 * g + 1], a[mt], br[g][1], br[g][3]);
                    }
                }
        }
    }

    if constexpr (EPI == 0) {
        const int qrow = lane >> 2;
        const int qcol = (lane & 3) * 2;
#pragma unroll
        for (int mt = 0; mt < 2; mt++) {
#pragma unroll
            for (int nt = 0; nt < 8; nt++) {
                int row = m0 + wm + mt * 16 + qrow;
                int col = n0 + wn + nt * 8 + qcol;
                float bx = 0.f, by = 0.f;
                if (BIAS) { bx = __ldg(&bias[col]); by = __ldg(&bias[col + 1]); }
                float2 v0 = make_float2(acc[mt][nt][0] + bx, acc[mt][nt][1] + by);
                float2 v1 = make_float2(acc[mt][nt][2] + bx, acc[mt][nt][3] + by);
                *(float2*)&C[(size_t)row * NTOT + col] = v0;
                *(float2*)&C[(size_t)(row + 8) * NTOT + col] = v1;
            }
        }
    } else {
        // -------- fused LSTM cell epilogue --------
        float* sh_h = (float*)smem;                 // [128][32]
        float* sh_c = (float*)(smem + 16384);       // [128][32]
        __syncthreads();
        {
            int rl = tid >> 1, half = (tid & 1) * 16;
            const float4* src = (const float4*)&cbuf[(size_t)(m0 + rl) * DD + (n0 >> 2) + half];
            float4* dst = (float4*)&sh_c[rl * 32 + half];
#pragma unroll
            for (int j = 0; j < 4; j++) dst[j] = src[j];
        }
        __syncthreads();

        const int qrow = lane >> 2;
        const bool odd = lane & 1;
#pragma unroll
        for (int mt = 0; mt < 2; mt++) {
#pragma unroll
            for (int nt = 0; nt < 8; nt++) {
                float* a = acc[mt][nt];
                float e0 = __shfl_xor_sync(0xFFFFFFFFu, a[0], 1);
                float e1 = __shfl_xor_sync(0xFFFFFFFFu, a[1], 1);
                float e2 = __shfl_xor_sync(0xFFFFFFFFu, a[2], 1);
                float e3 = __shfl_xor_sync(0xFFFFFFFFu, a[3], 1);
                float gi, gf, gg, go;
                if (!odd) { gi = a[0]; gf = a[1]; gg = e0; go = e1; }
                else      { gi = e2;   gf = e3;   gg = a[2]; go = a[3]; }
                int rl = wm + mt * 16 + qrow + (odd ? 8 : 0);
                int dl = (wn >> 2) + nt * 2 + ((lane & 3) >> 1);
                int p = m0 + rl;
                int d = (n0 >> 2) + dl;
                int l = p & 511;
                float4 q;
                if (l + step - 8 >= 0) {
                    q = *(const float4*)&gx[(size_t)(p + step - 8) * G4 + 4 * d];
                } else {
                    q = *(const float4*)&b0[4 * d];
                }
                gi += q.x;
                gf += q.y;
                gg += q.z;
                go += q.w;
                float c_old = sh_c[rl * 32 + dl];
                float c = sigf(gf) * c_old + sigf(gi) * tanhf(gg);
                float h = sigf(go) * tanhf(c);
                sh_c[rl * 32 + dl] = c;
                sh_h[rl * 32 + dl] = h;
            }
        }
        __syncthreads();
        {
            int rl = tid >> 1, half = (tid & 1) * 16;
            int p = m0 + rl;
            int dg = (n0 >> 2) + half;
            float4* ch = (float4*)&sh_c[rl * 32 + half];
            float4* hh4 = (float4*)&sh_h[rl * 32 + half];
#pragma unroll
            for (int j = 0; j < 4; j++)
                *(float4*)&cbuf[(size_t)p * DD + dg + 4 * j] = ch[j];
            if (step == KS - 1) {
#pragma unroll
                for (int j = 0; j < 4; j++)
                    *(float4*)&out[(size_t)p * DD + dg + 4 * j] = hh4[j];
            } else {
                uint32_t hv[8];
#pragma unroll
                for (int j = 0; j < 8; j++) {
                    __half h0 = __float2half_rn(sh_h[rl * 32 + half + 2 * j]);
                    __half h1 = __float2half_rn(sh_h[rl * 32 + half + 2 * j + 1]);
                    hv[j] = pack_h2(h0, h1);
                }
                size_t base = (size_t)p * DD + dg;
                *(uint4*)&h1out[base]     = make_uint4(hv[0], hv[1], hv[2], hv[3]);
                *(uint4*)&h1out[base + 8] = make_uint4(hv[4], hv[5], hv[6], hv[7]);
            }
        }
    }
}

// ---------------------------------------------------------------------------
// Elementwise / prep kernels
// ---------------------------------------------------------------------------
// GLU + fp16 hi/lo split -> g_glu2 = [gh(256) | gl(256)]
__global__ void glu2_kernel(const float* __restrict__ x) {
    int i = blockIdx.x * blockDim.x + threadIdx.x;
    if (i >= PP * DH) return;
    int p = i >> 8;
    int c = i & 255;
    float a = x[p * 512 + c];
    float b = x[p * 512 + 256 + c];
    float v = a * sigf(b);
    __half hi, lo;
    split2h(v, hi, lo);
    size_t base = (size_t)p * K2H;
    g_glu2[base + c] = hi;
    g_glu2[base + 256 + c] = lo;
}

// bf16 3-split A-style [hi|hi|lo] with gate interleave (Wf GEMM A operand)
__global__ void wsplit3a_kernel(const float* __restrict__ w,
                                __nv_bfloat16* __restrict__ dst, int K, int total) {
    int i = blockIdx.x * blockDim.x + threadIdx.x;
    if (i >= total) return;
    int n = i / K;
    int k = i - n * K;
    int nd = ((n & 511) << 2) + (n >> 9);
    __nv_bfloat16 hi, lo;
    split2b(w[i], hi, lo);
    size_t base = (size_t)nd * 3 * K;
    dst[base + k] = hi; dst[base + K + k] = hi; dst[base + 2 * K + k] = lo;
}

// w_hh -> fp16 rounded, gate-interleaved rows (plain 1x K)
__global__ void wround_kernel(const float* __restrict__ w,
                              __half* __restrict__ dst) {
    int i = blockIdx.x * blockDim.x + threadIdx.x;
    if (i >= G4 * DD) return;
    int n = i >> 9;
    int k = i & 511;
    int nd = ((n & 511) << 2) + (n >> 9);
    dst[(size_t)nd * DD + k] = __float2half_rn(w[i]);
}

// Wf (fp32) -> g_wf2 [hi|hi] (B of Gx GEMM)
__global__ void wfdup_kernel(const float* __restrict__ w) {
    int i = blockIdx.x * blockDim.x + threadIdx.x;
    if (i >= G4 * DH) return;
    int n = i >> 8;
    int k = i & 255;
    __half hi = __float2half_rn(w[i]);
    size_t base = (size_t)n * K2H;
    g_wf2[base + k] = hi;
    g_wf2[base + 256 + k] = hi;
}

// conv_w (512x256) -> g_cwT3[256][1536] bf16 B-style (transposed)
__global__ void wsplitT_kernel(const float* __restrict__ w) {
    int i = blockIdx.x * blockDim.x + threadIdx.x;
    if (i >= DD * DH) return;
    int d = i >> 8, c = i & 255;
    __nv_bfloat16 hi, lo;
    split2b(w[i], hi, lo);
    size_t base = (size_t)c * K3D;
    g_cwT3[base + d] = hi;
    g_cwT3[base + 512 + d] = lo;
    g_cwT3[base + 1024 + d] = hi;
}

// biases: g_bf[n'] = b_ih + w_ih.conv_b + b_hh;  g_b0[n'] = b_ih + b_hh
__global__ void bfvec_kernel(const float* __restrict__ w_ih,
                             const float* __restrict__ b_ih,
                             const float* __restrict__ b_hh,
                             const float* __restrict__ conv_b) {
    int gid = blockIdx.x * blockDim.x + threadIdx.x;
    int warp = gid >> 5;
    int lane = gid & 31;
    if (warp >= G4) return;
    int nsrc = ((warp & 3) << 9) + (warp >> 2);
    float s = 0.f;
#pragma unroll 4
    for (int k = lane; k < DD; k += 32)
        s += w_ih[(size_t)nsrc * DD + k] * conv_b[k];
#pragma unroll
    for (int o = 16; o; o >>= 1) s += __shfl_xor_sync(0xFFFFFFFFu, s, o);
    if (!lane) {
        float bb = b_ih[nsrc] + b_hh[nsrc];
        g_bf[warp] = s + bb;
        g_b0[warp] = bb;
    }
}

// step 0 cell (h=0, c=0); writes plain fp16 h
__global__ void cell0_kernel(__half* __restrict__ h1out) {
    int i = blockIdx.x * blockDim.x + threadIdx.x;
    if (i >= PP * DD) return;
    int p = i >> 9, d = i & 511, l = p & 511;
    float4 q;
    if (l - 8 >= 0) {
        q = *(const float4*)&g_gx[(size_t)(p - 8) * G4 + 4 * d];
    } else {
        q = *(const float4*)&g_b0[4 * d];
    }
    float c = sigf(q.x) * tanhf(q.z);
    float h = sigf(q.w) * tanhf(c);
    g_c[i] = c;
    h1out[i] = __float2half_rn(h);
}

// ---------------------------------------------------------------------------
// Launch
// ---------------------------------------------------------------------------
extern "C" void kernel_launch(void* const* d_in, const int* in_sizes, int n_in,
                              void* d_out, int out_size) {
    const float* x      = (const float*)d_in[0];
    const float* conv_w = (const float*)d_in[1];
    const float* conv_b = (const float*)d_in[2];
    const float* w_ih   = (const float*)d_in[3];
    const float* w_hh   = (const float*)d_in[4];
    const float* b_ih   = (const float*)d_in[5];
    const float* b_hh   = (const float*)d_in[6];
    float* out = (float*)d_out;

    __nv_bfloat16 *p_wih3, *p_cwT3;
    __half *p_glu2, *p_h1a, *p_h1b, *p_whh1, *p_wf2;
    float *p_gx, *p_c, *p_wf, *p_bf, *p_b0;
    cudaGetSymbolAddress((void**)&p_glu2, g_glu2);
    cudaGetSymbolAddress((void**)&p_gx, g_gx);
    cudaGetSymbolAddress((void**)&p_h1a, g_h1a);
    cudaGetSymbolAddress((void**)&p_h1b, g_h1b);
    cudaGetSymbolAddress((void**)&p_c, g_c);
    cudaGetSymbolAddress((void**)&p_wih3, g_wih3);
    cudaGetSymbolAddress((void**)&p_whh1, g_whh1);
    cudaGetSymbolAddress((void**)&p_cwT3, g_cwT3);
    cudaGetSymbolAddress((void**)&p_wf, g_wf);
    cudaGetSymbolAddress((void**)&p_wf2, g_wf2);
    cudaGetSymbolAddress((void**)&p_bf, g_bf);
    cudaGetSymbolAddress((void**)&p_b0, g_b0);

    cudaFuncSetAttribute(gemm_mma<__nv_bfloat16, K3D, DH, false, 0>,
                         cudaFuncAttributeMaxDynamicSharedMemorySize, SMEM_BYTES);
    cudaFuncSetAttribute(gemm_mma<__half, K2H, G4, true, 0>,
                         cudaFuncAttributeMaxDynamicSharedMemorySize, SMEM_BYTES);
    cudaFuncSetAttribute(gemm_mma<__half, DD, G4, false, 1>,
                         cudaFuncAttributeMaxDynamicSharedMemorySize, SMEM_BYTES);

    // 1) input prep
    glu2_kernel<<<(PP * DH + 255) / 256, 256>>>(x);
    wsplit3a_kernel<<<(G4 * DD + 255) / 256, 256>>>(w_ih, p_wih3, DD, G4 * DD);
    wround_kernel<<<(G4 * DD + 255) / 256, 256>>>(w_hh, p_whh1);
    wsplitT_kernel<<<(DD * DH + 255) / 256, 256>>>(conv_w);
    bfvec_kernel<<<(G4 * 32 + 255) / 256, 256>>>(w_ih, b_ih, b_hh, conv_b);

    // 2) Wf = w_ih @ conv_w (bf16 3-split, high accuracy), rows gate-interleaved
    gemm_mma<__nv_bfloat16, K3D, DH, false, 0><<<dim3(DH / 128, G4 / 128), 256, SMEM_BYTES>>>(
        p_wih3, p_cwT3, nullptr, p_wf,
        nullptr, nullptr, nullptr, nullptr, nullptr, 0);
    wfdup_kernel<<<(G4 * DH + 255) / 256, 256>>>(p_wf);

    // 3) Gx = glu @ Wf^T + bf  (fp16 2-split, K'=512), gate-interleaved output
    gemm_mma<__half, K2H, G4, true, 0><<<dim3(G4 / 128, PP / 128), 256, SMEM_BYTES>>>(
        p_glu2, p_wf2, p_bf, p_gx,
        nullptr, nullptr, nullptr, nullptr, nullptr, 0);

    // 4) step 0
    cell0_kernel<<<(PP * DD + 255) / 256, 256>>>(p_h1a);

    // 5) steps 1..8: recurrent GEMM (plain fp16, K=512) + fused cell
    __half* hping[2] = {p_h1a, p_h1b};
    for (int step = 1; step < KS; step++) {
        const __half* h_in = hping[(step - 1) & 1];
        __half* h_out = hping[step & 1];
        gemm_mma<__half, DD, G4, false, 1><<<dim3(G4 / 128, PP / 128), 256, SMEM_BYTES>>>(
            h_in, p_whh1, nullptr, nullptr,
            p_gx, p_b0, p_c, h_out, out, step);
    }
}